// round 1
// baseline (speedup 1.0000x reference)
#include <cuda_runtime.h>
#include <math.h>

// ---------------- problem constants ----------------
#define BATCH   2
#define CCH     1024          // channels / INNER
#define HW      1600          // 40*40 pixels
#define MTOK    (BATCH*HW)    // 3200 token rows
#define HEADS   16
#define DH      64
#define CTXL    77
#define FFD     4096
#define GN_GROUPS 32
#define GN_EPS  1e-6f
#define LN_EPS  1e-5f

// ---------------- scratch (device globals; no allocations allowed) ----------
__device__ float g_t   [MTOK * CCH];
__device__ float g_tmp [MTOK * CCH];
__device__ float g_q   [MTOK * CCH];
__device__ float g_k   [MTOK * CCH];
__device__ float g_v   [MTOK * CCH];
__device__ float g_ao  [MTOK * CCH];
__device__ float g_scores[(size_t)BATCH * HEADS * HW * HW];   // 81.92M floats
__device__ float g_ffh [MTOK * 2 * FFD];
__device__ float g_ffa [MTOK * FFD];

// ---------------- reductions ----------------
__device__ __forceinline__ float blockReduceSum(float v) {
    __shared__ float sh[32];
    int lane = threadIdx.x & 31, wid = threadIdx.x >> 5;
#pragma unroll
    for (int o = 16; o > 0; o >>= 1) v += __shfl_down_sync(0xffffffffu, v, o);
    if (lane == 0) sh[wid] = v;
    __syncthreads();
    int nw = (blockDim.x + 31) >> 5;
    v = (threadIdx.x < nw) ? sh[threadIdx.x] : 0.f;
    if (wid == 0) {
#pragma unroll
        for (int o = 16; o > 0; o >>= 1) v += __shfl_down_sync(0xffffffffu, v, o);
        if (lane == 0) sh[0] = v;
    }
    __syncthreads();
    float r = sh[0];
    __syncthreads();
    return r;
}

__device__ __forceinline__ float blockReduceMax(float v) {
    __shared__ float sh[32];
    int lane = threadIdx.x & 31, wid = threadIdx.x >> 5;
#pragma unroll
    for (int o = 16; o > 0; o >>= 1) v = fmaxf(v, __shfl_down_sync(0xffffffffu, v, o));
    if (lane == 0) sh[wid] = v;
    __syncthreads();
    int nw = (blockDim.x + 31) >> 5;
    v = (threadIdx.x < nw) ? sh[threadIdx.x] : -INFINITY;
    if (wid == 0) {
#pragma unroll
        for (int o = 16; o > 0; o >>= 1) v = fmaxf(v, __shfl_down_sync(0xffffffffu, v, o));
        if (lane == 0) sh[0] = v;
    }
    __syncthreads();
    float r = sh[0];
    __syncthreads();
    return r;
}

// ---------------- GroupNorm + transpose to [B, HW, C] ----------------
__global__ void groupnorm_kernel(const float* __restrict__ x,
                                 const float* __restrict__ s,
                                 const float* __restrict__ bgn,
                                 float* __restrict__ out) {
    int b = blockIdx.x / GN_GROUPS;
    int g = blockIdx.x % GN_GROUPS;
    const int CPG = CCH / GN_GROUPS;          // 32 channels per group
    const int NEL = CPG * HW;                 // 51200
    const float* xp = x + ((size_t)b * CCH + (size_t)g * CPG) * HW;

    float sum = 0.f, sq = 0.f;
    for (int i = threadIdx.x; i < NEL; i += blockDim.x) {
        float v = xp[i];
        sum += v; sq += v * v;
    }
    sum = blockReduceSum(sum);
    sq  = blockReduceSum(sq);
    float mean = sum / (float)NEL;
    float var  = sq / (float)NEL - mean * mean;
    float inv  = rsqrtf(var + GN_EPS);

    for (int i = threadIdx.x; i < NEL; i += blockDim.x) {
        int ci = i / HW;
        int p  = i % HW;
        int c  = g * CPG + ci;
        float v = (xp[i] - mean) * inv * s[c] + bgn[c];
        out[((size_t)b * HW + p) * CCH + c] = v;
    }
}

// ---------------- LayerNorm over last dim (cols=1024) ----------------
__global__ void layernorm_kernel(const float* __restrict__ x,
                                 const float* __restrict__ s,
                                 const float* __restrict__ b,
                                 float* __restrict__ out) {
    int row = blockIdx.x;
    const float* xr = x + (size_t)row * CCH;
    float sum = 0.f, sq = 0.f;
    for (int i = threadIdx.x; i < CCH; i += blockDim.x) {
        float v = xr[i];
        sum += v; sq += v * v;
    }
    sum = blockReduceSum(sum);
    sq  = blockReduceSum(sq);
    float mean = sum / (float)CCH;
    float var  = sq / (float)CCH - mean * mean;
    float inv  = rsqrtf(var + LN_EPS);
    float* o = out + (size_t)row * CCH;
    for (int i = threadIdx.x; i < CCH; i += blockDim.x)
        o[i] = (xr[i] - mean) * inv * s[i] + b[i];
}

// ---------------- generic tiled batched GEMM ----------------
// C[m,n] = alpha * sum_k A[m,k] * B(k,n)  (+bias[n]) (+res[m,n])
// TB=false: B(k,n) = Bm[k*ldb + n]; TB=true: B(k,n) = Bm[n*ldb + k]
template<bool TB>
__global__ __launch_bounds__(256)
void gemm_kernel(const float* __restrict__ A, const float* __restrict__ Bm,
                 const float* __restrict__ bias, const float* __restrict__ res,
                 float* __restrict__ C,
                 int M, int N, int K, int lda, int ldb, int ldc,
                 long long sAo, long long sAi, long long sBo, long long sBi,
                 long long sCo, long long sCi, int inner, float alpha) {
    int z  = blockIdx.z;
    int zo = z / inner, zi = z % inner;
    A  += (size_t)(zo * sAo + zi * sAi);
    Bm += (size_t)(zo * sBo + zi * sBi);
    long long coff = zo * sCo + zi * sCi;
    C += coff;
    if (res) res += coff;

    __shared__ float As[16][65];
    __shared__ float Bs[16][65];

    int tx = threadIdx.x % 16;
    int ty = threadIdx.x / 16;
    int tid = threadIdx.x;

    int rowBase = blockIdx.y * 64;
    int colBase = blockIdx.x * 64;

    float acc[4][4];
#pragma unroll
    for (int i = 0; i < 4; i++)
#pragma unroll
        for (int j = 0; j < 4; j++) acc[i][j] = 0.f;

    int ktiles = (K + 15) / 16;
    for (int kt = 0; kt < ktiles; kt++) {
        int k0 = kt * 16;
        // load A tile: 64 x 16
#pragma unroll
        for (int e = tid; e < 1024; e += 256) {
            int m = e / 16, k = e % 16;
            int gm = rowBase + m, gk = k0 + k;
            As[k][m] = (gm < M && gk < K) ? A[(size_t)gm * lda + gk] : 0.f;
        }
        // load B tile: 16 x 64
        if (!TB) {
#pragma unroll
            for (int e = tid; e < 1024; e += 256) {
                int k = e / 64, n = e % 64;
                int gk = k0 + k, gn = colBase + n;
                Bs[k][n] = (gk < K && gn < N) ? Bm[(size_t)gk * ldb + gn] : 0.f;
            }
        } else {
#pragma unroll
            for (int e = tid; e < 1024; e += 256) {
                int n = e / 16, k = e % 16;
                int gk = k0 + k, gn = colBase + n;
                Bs[k][n] = (gk < K && gn < N) ? Bm[(size_t)gn * ldb + gk] : 0.f;
            }
        }
        __syncthreads();
#pragma unroll
        for (int k = 0; k < 16; k++) {
            float a[4], bb[4];
#pragma unroll
            for (int i = 0; i < 4; i++) a[i] = As[k][ty * 4 + i];
#pragma unroll
            for (int j = 0; j < 4; j++) bb[j] = Bs[k][tx * 4 + j];
#pragma unroll
            for (int i = 0; i < 4; i++)
#pragma unroll
                for (int j = 0; j < 4; j++) acc[i][j] += a[i] * bb[j];
        }
        __syncthreads();
    }

#pragma unroll
    for (int i = 0; i < 4; i++) {
        int row = rowBase + ty * 4 + i;
        if (row >= M) continue;
#pragma unroll
        for (int j = 0; j < 4; j++) {
            int col = colBase + tx * 4 + j;
            if (col >= N) continue;
            float v = acc[i][j] * alpha;
            if (bias) v += bias[col];
            if (res)  v += res[(size_t)row * ldc + col];
            C[(size_t)row * ldc + col] = v;
        }
    }
}

// ---------------- softmax over rows ----------------
__global__ void softmax_kernel(float* __restrict__ sc, int len) {
    float* p = sc + (size_t)blockIdx.x * len;
    float mx = -INFINITY;
    for (int i = threadIdx.x; i < len; i += blockDim.x) mx = fmaxf(mx, p[i]);
    mx = blockReduceMax(mx);
    float sum = 0.f;
    for (int i = threadIdx.x; i < len; i += blockDim.x) {
        float e = expf(p[i] - mx);
        p[i] = e;
        sum += e;
    }
    sum = blockReduceSum(sum);
    float inv = 1.f / sum;
    for (int i = threadIdx.x; i < len; i += blockDim.x) p[i] *= inv;
}

// ---------------- GEGLU ----------------
__global__ void geglu_kernel(const float* __restrict__ h, float* __restrict__ out) {
    size_t idx = (size_t)blockIdx.x * blockDim.x + threadIdx.x;
    size_t total = (size_t)MTOK * FFD;
    if (idx >= total) return;
    size_t row = idx / FFD;
    size_t col = idx % FFD;
    float a = h[row * (2 * FFD) + col];
    float g = h[row * (2 * FFD) + FFD + col];
    float gelu = 0.5f * g * (1.f + erff(g * 0.70710678118654752f));
    out[idx] = a * gelu;
}

// ---------------- final transpose + residual ----------------
__global__ void final_kernel(const float* __restrict__ proj,
                             const float* __restrict__ x,
                             float* __restrict__ out) {
    size_t idx = (size_t)blockIdx.x * blockDim.x + threadIdx.x;
    size_t total = (size_t)BATCH * CCH * HW;
    if (idx >= total) return;
    size_t p  = idx % HW;
    size_t bc = idx / HW;
    size_t c  = bc % CCH;
    size_t b  = bc / CCH;
    out[idx] = proj[((size_t)b * HW + p) * CCH + c] + x[idx];
}

// ---------------- host side ----------------
static void launch_gemm(bool tb, const float* A, const float* B, const float* bias,
                        const float* res, float* C, int M, int N, int K,
                        int lda, int ldb, int ldc,
                        int batches, int inner,
                        long long sAo, long long sAi, long long sBo, long long sBi,
                        long long sCo, long long sCi, float alpha) {
    dim3 grid((N + 63) / 64, (M + 63) / 64, batches);
    dim3 block(256);
    if (tb)
        gemm_kernel<true><<<grid, block>>>(A, B, bias, res, C, M, N, K, lda, ldb, ldc,
                                           sAo, sAi, sBo, sBi, sCo, sCi, inner, alpha);
    else
        gemm_kernel<false><<<grid, block>>>(A, B, bias, res, C, M, N, K, lda, ldb, ldc,
                                            sAo, sAi, sBo, sBi, sCo, sCi, inner, alpha);
}

extern "C" void kernel_launch(void* const* d_in, const int* in_sizes, int n_in,
                              void* d_out, int out_size) {
    const float* x      = (const float*)d_in[0];
    const float* ctx    = (const float*)d_in[1];
    const float* gn_s   = (const float*)d_in[2];
    const float* gn_b   = (const float*)d_in[3];
    const float* pin_w  = (const float*)d_in[4];
    const float* pin_b  = (const float*)d_in[5];
    const float* ln1_s  = (const float*)d_in[6];
    const float* ln1_b  = (const float*)d_in[7];
    const float* wq1    = (const float*)d_in[8];
    const float* wk1    = (const float*)d_in[9];
    const float* wv1    = (const float*)d_in[10];
    const float* wo1    = (const float*)d_in[11];
    const float* bo1    = (const float*)d_in[12];
    const float* ln2_s  = (const float*)d_in[13];
    const float* ln2_b  = (const float*)d_in[14];
    const float* wq2    = (const float*)d_in[15];
    const float* wk2    = (const float*)d_in[16];
    const float* wv2    = (const float*)d_in[17];
    const float* wo2    = (const float*)d_in[18];
    const float* bo2    = (const float*)d_in[19];
    const float* ln3_s  = (const float*)d_in[20];
    const float* ln3_b  = (const float*)d_in[21];
    const float* ff_w1  = (const float*)d_in[22];
    const float* ff_b1  = (const float*)d_in[23];
    const float* ff_w2  = (const float*)d_in[24];
    const float* ff_b2  = (const float*)d_in[25];
    const float* pout_w = (const float*)d_in[26];
    const float* pout_b = (const float*)d_in[27];
    float* out = (float*)d_out;

    float *t, *tmp, *q, *k, *v, *ao, *scores, *ffh, *ffa;
    cudaGetSymbolAddress((void**)&t,      g_t);
    cudaGetSymbolAddress((void**)&tmp,    g_tmp);
    cudaGetSymbolAddress((void**)&q,      g_q);
    cudaGetSymbolAddress((void**)&k,      g_k);
    cudaGetSymbolAddress((void**)&v,      g_v);
    cudaGetSymbolAddress((void**)&ao,     g_ao);
    cudaGetSymbolAddress((void**)&scores, g_scores);
    cudaGetSymbolAddress((void**)&ffh,    g_ffh);
    cudaGetSymbolAddress((void**)&ffa,    g_ffa);

    const float attn_scale = 0.125f;   // 64^-0.5

    // 1. GroupNorm + transpose -> tmp [B, HW, C]
    groupnorm_kernel<<<BATCH * GN_GROUPS, 256>>>(x, gn_s, gn_b, tmp);

    // 2. proj_in: t = tmp @ pin_w + pin_b
    launch_gemm(false, tmp, pin_w, pin_b, nullptr, t, MTOK, CCH, CCH, CCH, CCH, CCH,
                1, 1, 0, 0, 0, 0, 0, 0, 1.f);

    // ---- self-attention ----
    layernorm_kernel<<<MTOK, 256>>>(t, ln1_s, ln1_b, tmp);
    launch_gemm(false, tmp, wq1, nullptr, nullptr, q, MTOK, CCH, CCH, CCH, CCH, CCH,
                1, 1, 0, 0, 0, 0, 0, 0, 1.f);
    launch_gemm(false, tmp, wk1, nullptr, nullptr, k, MTOK, CCH, CCH, CCH, CCH, CCH,
                1, 1, 0, 0, 0, 0, 0, 0, 1.f);
    launch_gemm(false, tmp, wv1, nullptr, nullptr, v, MTOK, CCH, CCH, CCH, CCH, CCH,
                1, 1, 0, 0, 0, 0, 0, 0, 1.f);
    // scores[b,h,i,j] = scale * q . k
    launch_gemm(true, q, k, nullptr, nullptr, scores, HW, HW, DH, CCH, CCH, HW,
                BATCH * HEADS, HEADS,
                (long long)HW * CCH, DH, (long long)HW * CCH, DH,
                (long long)HEADS * HW * HW, (long long)HW * HW, attn_scale);
    softmax_kernel<<<BATCH * HEADS * HW, 256>>>(scores, HW);
    // ao[b,i,h,d] = attn @ v
    launch_gemm(false, scores, v, nullptr, nullptr, ao, HW, DH, HW, HW, CCH, CCH,
                BATCH * HEADS, HEADS,
                (long long)HEADS * HW * HW, (long long)HW * HW,
                (long long)HW * CCH, DH,
                (long long)HW * CCH, DH, 1.f);
    // o1 + residual
    launch_gemm(false, ao, wo1, bo1, t, t, MTOK, CCH, CCH, CCH, CCH, CCH,
                1, 1, 0, 0, 0, 0, 0, 0, 1.f);

    // ---- cross-attention ----
    layernorm_kernel<<<MTOK, 256>>>(t, ln2_s, ln2_b, tmp);
    launch_gemm(false, tmp, wq2, nullptr, nullptr, q, MTOK, CCH, CCH, CCH, CCH, CCH,
                1, 1, 0, 0, 0, 0, 0, 0, 1.f);
    launch_gemm(false, ctx, wk2, nullptr, nullptr, k, BATCH * CTXL, CCH, CCH, CCH, CCH, CCH,
                1, 1, 0, 0, 0, 0, 0, 0, 1.f);
    launch_gemm(false, ctx, wv2, nullptr, nullptr, v, BATCH * CTXL, CCH, CCH, CCH, CCH, CCH,
                1, 1, 0, 0, 0, 0, 0, 0, 1.f);
    launch_gemm(true, q, k, nullptr, nullptr, scores, HW, CTXL, DH, CCH, CCH, CTXL,
                BATCH * HEADS, HEADS,
                (long long)HW * CCH, DH, (long long)CTXL * CCH, DH,
                (long long)HEADS * HW * CTXL, (long long)HW * CTXL, attn_scale);
    softmax_kernel<<<BATCH * HEADS * HW, 256>>>(scores, CTXL);
    launch_gemm(false, scores, v, nullptr, nullptr, ao, HW, DH, CTXL, CTXL, CCH, CCH,
                BATCH * HEADS, HEADS,
                (long long)HEADS * HW * CTXL, (long long)HW * CTXL,
                (long long)CTXL * CCH, DH,
                (long long)HW * CCH, DH, 1.f);
    launch_gemm(false, ao, wo2, bo2, t, t, MTOK, CCH, CCH, CCH, CCH, CCH,
                1, 1, 0, 0, 0, 0, 0, 0, 1.f);

    // ---- GEGLU FF ----
    layernorm_kernel<<<MTOK, 256>>>(t, ln3_s, ln3_b, tmp);
    launch_gemm(false, tmp, ff_w1, ff_b1, nullptr, ffh, MTOK, 2 * FFD, CCH,
                CCH, 2 * FFD, 2 * FFD, 1, 1, 0, 0, 0, 0, 0, 0, 1.f);
    {
        size_t total = (size_t)MTOK * FFD;
        geglu_kernel<<<(int)((total + 255) / 256), 256>>>(ffh, ffa);
    }
    launch_gemm(false, ffa, ff_w2, ff_b2, t, t, MTOK, CCH, FFD, FFD, CCH, CCH,
                1, 1, 0, 0, 0, 0, 0, 0, 1.f);

    // ---- proj_out + residual ----
    launch_gemm(false, t, pout_w, pout_b, nullptr, tmp, MTOK, CCH, CCH, CCH, CCH, CCH,
                1, 1, 0, 0, 0, 0, 0, 0, 1.f);
    {
        size_t total = (size_t)BATCH * CCH * HW;
        final_kernel<<<(int)((total + 255) / 256), 256>>>(tmp, x, out);
    }
}

// round 2
// speedup vs baseline: 2.1546x; 2.1546x over previous
#include <cuda_runtime.h>
#include <math.h>
#include <stdint.h>

// ---------------- problem constants ----------------
#define BATCH   2
#define CCH     1024          // channels / INNER
#define HW      1600          // 40*40 pixels
#define MTOK    (BATCH*HW)    // 3200 token rows
#define HEADS   16
#define DH      64
#define CTXL    77
#define FFD     4096
#define GN_GROUPS 32
#define GN_EPS  1e-6f
#define LN_EPS  1e-5f

// ---------------- scratch (device globals; no allocations allowed) ----------
__device__ float g_t   [MTOK * CCH];
__device__ float g_tmp [MTOK * CCH];
__device__ float g_q   [MTOK * CCH];
__device__ float g_k   [MTOK * CCH];
__device__ float g_v   [MTOK * CCH];
__device__ float g_ao  [MTOK * CCH];
__device__ float g_scores[(size_t)BATCH * HEADS * HW * HW];
__device__ float g_ffh [MTOK * 2 * FFD];
__device__ float g_ffa [MTOK * FFD];

// ---------------- reductions ----------------
__device__ __forceinline__ float blockReduceSum(float v) {
    __shared__ float sh[32];
    int lane = threadIdx.x & 31, wid = threadIdx.x >> 5;
#pragma unroll
    for (int o = 16; o > 0; o >>= 1) v += __shfl_down_sync(0xffffffffu, v, o);
    if (lane == 0) sh[wid] = v;
    __syncthreads();
    int nw = (blockDim.x + 31) >> 5;
    v = (threadIdx.x < nw) ? sh[threadIdx.x] : 0.f;
    if (wid == 0) {
#pragma unroll
        for (int o = 16; o > 0; o >>= 1) v += __shfl_down_sync(0xffffffffu, v, o);
        if (lane == 0) sh[0] = v;
    }
    __syncthreads();
    float r = sh[0];
    __syncthreads();
    return r;
}

__device__ __forceinline__ float blockReduceMax(float v) {
    __shared__ float sh[32];
    int lane = threadIdx.x & 31, wid = threadIdx.x >> 5;
#pragma unroll
    for (int o = 16; o > 0; o >>= 1) v = fmaxf(v, __shfl_down_sync(0xffffffffu, v, o));
    if (lane == 0) sh[wid] = v;
    __syncthreads();
    int nw = (blockDim.x + 31) >> 5;
    v = (threadIdx.x < nw) ? sh[threadIdx.x] : -INFINITY;
    if (wid == 0) {
#pragma unroll
        for (int o = 16; o > 0; o >>= 1) v = fmaxf(v, __shfl_down_sync(0xffffffffu, v, o));
        if (lane == 0) sh[0] = v;
    }
    __syncthreads();
    float r = sh[0];
    __syncthreads();
    return r;
}

// ---------------- GroupNorm + transpose to [B, HW, C] ----------------
__global__ void groupnorm_kernel(const float* __restrict__ x,
                                 const float* __restrict__ s,
                                 const float* __restrict__ bgn,
                                 float* __restrict__ out) {
    int b = blockIdx.x / GN_GROUPS;
    int g = blockIdx.x % GN_GROUPS;
    const int CPG = CCH / GN_GROUPS;
    const int NEL = CPG * HW;
    const float* xp = x + ((size_t)b * CCH + (size_t)g * CPG) * HW;

    float sum = 0.f, sq = 0.f;
    for (int i = threadIdx.x; i < NEL; i += blockDim.x) {
        float v = xp[i];
        sum += v; sq += v * v;
    }
    sum = blockReduceSum(sum);
    sq  = blockReduceSum(sq);
    float mean = sum / (float)NEL;
    float var  = sq / (float)NEL - mean * mean;
    float inv  = rsqrtf(var + GN_EPS);

    for (int i = threadIdx.x; i < NEL; i += blockDim.x) {
        int ci = i / HW;
        int p  = i % HW;
        int c  = g * CPG + ci;
        float v = (xp[i] - mean) * inv * s[c] + bgn[c];
        out[((size_t)b * HW + p) * CCH + c] = v;
    }
}

// ---------------- LayerNorm ----------------
__global__ void layernorm_kernel(const float* __restrict__ x,
                                 const float* __restrict__ s,
                                 const float* __restrict__ b,
                                 float* __restrict__ out) {
    int row = blockIdx.x;
    const float* xr = x + (size_t)row * CCH;
    float sum = 0.f, sq = 0.f;
    for (int i = threadIdx.x; i < CCH; i += blockDim.x) {
        float v = xr[i];
        sum += v; sq += v * v;
    }
    sum = blockReduceSum(sum);
    sq  = blockReduceSum(sq);
    float mean = sum / (float)CCH;
    float var  = sq / (float)CCH - mean * mean;
    float inv  = rsqrtf(var + LN_EPS);
    float* o = out + (size_t)row * CCH;
    for (int i = threadIdx.x; i < CCH; i += blockDim.x)
        o[i] = (xr[i] - mean) * inv * s[i] + b[i];
}

// ---------------- tf32 helpers ----------------
__device__ __forceinline__ float f2tf32(float x) {
    uint32_t u;
    asm("cvt.rna.tf32.f32 %0, %1;" : "=r"(u) : "f"(x));
    return __uint_as_float(u);
}

__device__ __forceinline__ void mma_tf32(float c[4], const uint32_t a[4],
                                         uint32_t b0, uint32_t b1) {
    asm volatile(
        "mma.sync.aligned.m16n8k8.row.col.f32.tf32.tf32.f32 "
        "{%0,%1,%2,%3}, {%4,%5,%6,%7}, {%8,%9}, {%0,%1,%2,%3};"
        : "+f"(c[0]), "+f"(c[1]), "+f"(c[2]), "+f"(c[3])
        : "r"(a[0]), "r"(a[1]), "r"(a[2]), "r"(a[3]), "r"(b0), "r"(b1));
}

// ---------------- tf32 tensor-core batched GEMM ----------------
// C = alpha * A @ B (+bias) (+res). 128x128 block tile, 8 warps of 32x64.
// TB=false: B(k,n)=Bm[k*ldb+n]; TB=true: B(k,n)=Bm[n*ldb+k].
#define SMSTRIDE 136
template<bool TB>
__global__ __launch_bounds__(256)
void mma_gemm_kernel(const float* __restrict__ A, const float* __restrict__ Bm,
                     const float* __restrict__ bias, const float* __restrict__ res,
                     float* __restrict__ C,
                     int M, int N, int K, int lda, int ldb, int ldc,
                     long long sAo, long long sAi, long long sBo, long long sBi,
                     long long sCo, long long sCi, int inner, float alpha) {
    int z  = blockIdx.z;
    int zo = z / inner, zi = z % inner;
    A  += (size_t)(zo * sAo + zi * sAi);
    Bm += (size_t)(zo * sBo + zi * sBi);
    long long coff = zo * sCo + zi * sCi;
    C += coff;
    if (res) res += coff;

    __shared__ float As[2][16][SMSTRIDE];
    __shared__ float Bs[2][16][SMSTRIDE];

    const int tid  = threadIdx.x;
    const int wid  = tid >> 5;
    const int lane = tid & 31;
    const int wr   = wid >> 1;          // warp row 0..3 (32 rows each)
    const int wc   = wid & 1;           // warp col 0..1 (64 cols each)
    const int warpM = wr * 32;
    const int warpN = wc * 64;
    const int mBase = blockIdx.y * 128;
    const int nBase = blockIdx.x * 128;
    const int gp = lane >> 2;           // 0..7
    const int tg = lane & 3;            // 0..3

    float acc[2][8][4];
#pragma unroll
    for (int i = 0; i < 2; i++)
#pragma unroll
        for (int j = 0; j < 8; j++)
#pragma unroll
            for (int q = 0; q < 4; q++) acc[i][j][q] = 0.f;

    float ra[8], rb[8];
    const int ktiles = (K + 15) / 16;

    // ---- prologue: load tile 0 ----
    {
        const int k0 = 0;
#pragma unroll
        for (int u = 0; u < 8; u++) {
            int e = u * 256 + tid;
            int row = e >> 4, kk = e & 15;
            int gm = mBase + row, gk = k0 + kk;
            ra[u] = (gm < M && gk < K) ? A[(size_t)gm * lda + gk] : 0.f;
        }
        if (!TB) {
#pragma unroll
            for (int u = 0; u < 8; u++) {
                int e = u * 256 + tid;
                int kk = e >> 7, n = e & 127;
                int gk = k0 + kk, gn = nBase + n;
                rb[u] = (gk < K && gn < N) ? Bm[(size_t)gk * ldb + gn] : 0.f;
            }
        } else {
#pragma unroll
            for (int u = 0; u < 8; u++) {
                int e = u * 256 + tid;
                int n = e >> 4, kk = e & 15;
                int gk = k0 + kk, gn = nBase + n;
                rb[u] = (gk < K && gn < N) ? Bm[(size_t)gn * ldb + gk] : 0.f;
            }
        }
#pragma unroll
        for (int u = 0; u < 8; u++) {
            int e = u * 256 + tid;
            As[0][e & 15][e >> 4] = f2tf32(ra[u]);
        }
        if (!TB) {
#pragma unroll
            for (int u = 0; u < 8; u++) {
                int e = u * 256 + tid;
                Bs[0][e >> 7][e & 127] = f2tf32(rb[u]);
            }
        } else {
#pragma unroll
            for (int u = 0; u < 8; u++) {
                int e = u * 256 + tid;
                Bs[0][e & 15][e >> 4] = f2tf32(rb[u]);
            }
        }
    }
    __syncthreads();

    for (int kt = 0; kt < ktiles; kt++) {
        int buf = kt & 1;
        // ---- prefetch next tile into regs ----
        if (kt + 1 < ktiles) {
            const int k0 = (kt + 1) * 16;
#pragma unroll
            for (int u = 0; u < 8; u++) {
                int e = u * 256 + tid;
                int row = e >> 4, kk = e & 15;
                int gm = mBase + row, gk = k0 + kk;
                ra[u] = (gm < M && gk < K) ? A[(size_t)gm * lda + gk] : 0.f;
            }
            if (!TB) {
#pragma unroll
                for (int u = 0; u < 8; u++) {
                    int e = u * 256 + tid;
                    int kk = e >> 7, n = e & 127;
                    int gk = k0 + kk, gn = nBase + n;
                    rb[u] = (gk < K && gn < N) ? Bm[(size_t)gk * ldb + gn] : 0.f;
                }
            } else {
#pragma unroll
                for (int u = 0; u < 8; u++) {
                    int e = u * 256 + tid;
                    int n = e >> 4, kk = e & 15;
                    int gk = k0 + kk, gn = nBase + n;
                    rb[u] = (gk < K && gn < N) ? Bm[(size_t)gn * ldb + gk] : 0.f;
                }
            }
        }

        // ---- compute on buf ----
#pragma unroll
        for (int ks = 0; ks < 2; ks++) {
            const int kb = ks * 8;
            uint32_t af[2][4];
#pragma unroll
            for (int i = 0; i < 2; i++) {
                int mr = warpM + i * 16 + gp;
                af[i][0] = __float_as_uint(As[buf][kb + tg    ][mr]);
                af[i][1] = __float_as_uint(As[buf][kb + tg    ][mr + 8]);
                af[i][2] = __float_as_uint(As[buf][kb + tg + 4][mr]);
                af[i][3] = __float_as_uint(As[buf][kb + tg + 4][mr + 8]);
            }
#pragma unroll
            for (int j = 0; j < 8; j++) {
                uint32_t b0 = __float_as_uint(Bs[buf][kb + tg    ][warpN + j * 8 + gp]);
                uint32_t b1 = __float_as_uint(Bs[buf][kb + tg + 4][warpN + j * 8 + gp]);
#pragma unroll
                for (int i = 0; i < 2; i++)
                    mma_tf32(acc[i][j], af[i], b0, b1);
            }
        }

        // ---- store prefetched tile to other buffer ----
        if (kt + 1 < ktiles) {
            int nbuf = buf ^ 1;
#pragma unroll
            for (int u = 0; u < 8; u++) {
                int e = u * 256 + tid;
                As[nbuf][e & 15][e >> 4] = f2tf32(ra[u]);
            }
            if (!TB) {
#pragma unroll
                for (int u = 0; u < 8; u++) {
                    int e = u * 256 + tid;
                    Bs[nbuf][e >> 7][e & 127] = f2tf32(rb[u]);
                }
            } else {
#pragma unroll
                for (int u = 0; u < 8; u++) {
                    int e = u * 256 + tid;
                    Bs[nbuf][e & 15][e >> 4] = f2tf32(rb[u]);
                }
            }
        }
        __syncthreads();
    }

    // ---- epilogue ----
#pragma unroll
    for (int i = 0; i < 2; i++) {
#pragma unroll
        for (int j = 0; j < 8; j++) {
            int r0 = mBase + warpM + i * 16 + gp;
            int c0 = nBase + warpN + j * 8 + tg * 2;
#pragma unroll
            for (int q = 0; q < 4; q++) {
                int row = r0 + (q >> 1) * 8;
                int col = c0 + (q & 1);
                if (row < M && col < N) {
                    float v = acc[i][j][q] * alpha;
                    if (bias) v += bias[col];
                    if (res)  v += res[(size_t)row * ldc + col];
                    C[(size_t)row * ldc + col] = v;
                }
            }
        }
    }
}

// ---------------- softmax (row cached in smem) ----------------
__global__ void softmax_kernel(float* __restrict__ sc, int len) {
    __shared__ float rowbuf[HW];   // max row length 1600
    float* p = sc + (size_t)blockIdx.x * len;
    float mx = -INFINITY;
    for (int i = threadIdx.x; i < len; i += blockDim.x) {
        float v = p[i];
        rowbuf[i] = v;
        mx = fmaxf(mx, v);
    }
    mx = blockReduceMax(mx);
    float sum = 0.f;
    for (int i = threadIdx.x; i < len; i += blockDim.x) {
        float e = __expf(rowbuf[i] - mx);
        rowbuf[i] = e;
        sum += e;
    }
    sum = blockReduceSum(sum);
    float inv = 1.f / sum;
    for (int i = threadIdx.x; i < len; i += blockDim.x)
        p[i] = rowbuf[i] * inv;
}

// ---------------- GEGLU ----------------
__global__ void geglu_kernel(const float* __restrict__ h, float* __restrict__ out) {
    size_t idx = (size_t)blockIdx.x * blockDim.x + threadIdx.x;
    size_t total = (size_t)MTOK * FFD;
    if (idx >= total) return;
    size_t row = idx / FFD;
    size_t col = idx % FFD;
    float a = h[row * (2 * FFD) + col];
    float g = h[row * (2 * FFD) + FFD + col];
    float gelu = 0.5f * g * (1.f + erff(g * 0.70710678118654752f));
    out[idx] = a * gelu;
}

// ---------------- final transpose + residual ----------------
__global__ void final_kernel(const float* __restrict__ proj,
                             const float* __restrict__ x,
                             float* __restrict__ out) {
    size_t idx = (size_t)blockIdx.x * blockDim.x + threadIdx.x;
    size_t total = (size_t)BATCH * CCH * HW;
    if (idx >= total) return;
    size_t p  = idx % HW;
    size_t bc = idx / HW;
    size_t c  = bc % CCH;
    size_t b  = bc / CCH;
    out[idx] = proj[((size_t)b * HW + p) * CCH + c] + x[idx];
}

// ---------------- host side ----------------
static void launch_gemm(bool tb, const float* A, const float* B, const float* bias,
                        const float* res, float* C, int M, int N, int K,
                        int lda, int ldb, int ldc,
                        int batches, int inner,
                        long long sAo, long long sAi, long long sBo, long long sBi,
                        long long sCo, long long sCi, float alpha) {
    dim3 grid((N + 127) / 128, (M + 127) / 128, batches);
    dim3 block(256);
    if (tb)
        mma_gemm_kernel<true><<<grid, block>>>(A, B, bias, res, C, M, N, K, lda, ldb, ldc,
                                               sAo, sAi, sBo, sBi, sCo, sCi, inner, alpha);
    else
        mma_gemm_kernel<false><<<grid, block>>>(A, B, bias, res, C, M, N, K, lda, ldb, ldc,
                                                sAo, sAi, sBo, sBi, sCo, sCi, inner, alpha);
}

extern "C" void kernel_launch(void* const* d_in, const int* in_sizes, int n_in,
                              void* d_out, int out_size) {
    const float* x      = (const float*)d_in[0];
    const float* ctx    = (const float*)d_in[1];
    const float* gn_s   = (const float*)d_in[2];
    const float* gn_b   = (const float*)d_in[3];
    const float* pin_w  = (const float*)d_in[4];
    const float* pin_b  = (const float*)d_in[5];
    const float* ln1_s  = (const float*)d_in[6];
    const float* ln1_b  = (const float*)d_in[7];
    const float* wq1    = (const float*)d_in[8];
    const float* wk1    = (const float*)d_in[9];
    const float* wv1    = (const float*)d_in[10];
    const float* wo1    = (const float*)d_in[11];
    const float* bo1    = (const float*)d_in[12];
    const float* ln2_s  = (const float*)d_in[13];
    const float* ln2_b  = (const float*)d_in[14];
    const float* wq2    = (const float*)d_in[15];
    const float* wk2    = (const float*)d_in[16];
    const float* wv2    = (const float*)d_in[17];
    const float* wo2    = (const float*)d_in[18];
    const float* bo2    = (const float*)d_in[19];
    const float* ln3_s  = (const float*)d_in[20];
    const float* ln3_b  = (const float*)d_in[21];
    const float* ff_w1  = (const float*)d_in[22];
    const float* ff_b1  = (const float*)d_in[23];
    const float* ff_w2  = (const float*)d_in[24];
    const float* ff_b2  = (const float*)d_in[25];
    const float* pout_w = (const float*)d_in[26];
    const float* pout_b = (const float*)d_in[27];
    float* out = (float*)d_out;

    float *t, *tmp, *q, *k, *v, *ao, *scores, *ffh, *ffa;
    cudaGetSymbolAddress((void**)&t,      g_t);
    cudaGetSymbolAddress((void**)&tmp,    g_tmp);
    cudaGetSymbolAddress((void**)&q,      g_q);
    cudaGetSymbolAddress((void**)&k,      g_k);
    cudaGetSymbolAddress((void**)&v,      g_v);
    cudaGetSymbolAddress((void**)&ao,     g_ao);
    cudaGetSymbolAddress((void**)&scores, g_scores);
    cudaGetSymbolAddress((void**)&ffh,    g_ffh);
    cudaGetSymbolAddress((void**)&ffa,    g_ffa);

    const float attn_scale = 0.125f;   // 64^-0.5

    // 1. GroupNorm + transpose -> tmp [B, HW, C]
    groupnorm_kernel<<<BATCH * GN_GROUPS, 256>>>(x, gn_s, gn_b, tmp);

    // 2. proj_in
    launch_gemm(false, tmp, pin_w, pin_b, nullptr, t, MTOK, CCH, CCH, CCH, CCH, CCH,
                1, 1, 0, 0, 0, 0, 0, 0, 1.f);

    // ---- self-attention ----
    layernorm_kernel<<<MTOK, 256>>>(t, ln1_s, ln1_b, tmp);
    launch_gemm(false, tmp, wq1, nullptr, nullptr, q, MTOK, CCH, CCH, CCH, CCH, CCH,
                1, 1, 0, 0, 0, 0, 0, 0, 1.f);
    launch_gemm(false, tmp, wk1, nullptr, nullptr, k, MTOK, CCH, CCH, CCH, CCH, CCH,
                1, 1, 0, 0, 0, 0, 0, 0, 1.f);
    launch_gemm(false, tmp, wv1, nullptr, nullptr, v, MTOK, CCH, CCH, CCH, CCH, CCH,
                1, 1, 0, 0, 0, 0, 0, 0, 1.f);
    launch_gemm(true, q, k, nullptr, nullptr, scores, HW, HW, DH, CCH, CCH, HW,
                BATCH * HEADS, HEADS,
                (long long)HW * CCH, DH, (long long)HW * CCH, DH,
                (long long)HEADS * HW * HW, (long long)HW * HW, attn_scale);
    softmax_kernel<<<BATCH * HEADS * HW, 256>>>(scores, HW);
    launch_gemm(false, scores, v, nullptr, nullptr, ao, HW, DH, HW, HW, CCH, CCH,
                BATCH * HEADS, HEADS,
                (long long)HEADS * HW * HW, (long long)HW * HW,
                (long long)HW * CCH, DH,
                (long long)HW * CCH, DH, 1.f);
    launch_gemm(false, ao, wo1, bo1, t, t, MTOK, CCH, CCH, CCH, CCH, CCH,
                1, 1, 0, 0, 0, 0, 0, 0, 1.f);

    // ---- cross-attention ----
    layernorm_kernel<<<MTOK, 256>>>(t, ln2_s, ln2_b, tmp);
    launch_gemm(false, tmp, wq2, nullptr, nullptr, q, MTOK, CCH, CCH, CCH, CCH, CCH,
                1, 1, 0, 0, 0, 0, 0, 0, 1.f);
    launch_gemm(false, ctx, wk2, nullptr, nullptr, k, BATCH * CTXL, CCH, CCH, CCH, CCH, CCH,
                1, 1, 0, 0, 0, 0, 0, 0, 1.f);
    launch_gemm(false, ctx, wv2, nullptr, nullptr, v, BATCH * CTXL, CCH, CCH, CCH, CCH, CCH,
                1, 1, 0, 0, 0, 0, 0, 0, 1.f);
    launch_gemm(true, q, k, nullptr, nullptr, scores, HW, CTXL, DH, CCH, CCH, CTXL,
                BATCH * HEADS, HEADS,
                (long long)HW * CCH, DH, (long long)CTXL * CCH, DH,
                (long long)HEADS * HW * CTXL, (long long)HW * CTXL, attn_scale);
    softmax_kernel<<<BATCH * HEADS * HW, 256>>>(scores, CTXL);
    launch_gemm(false, scores, v, nullptr, nullptr, ao, HW, DH, CTXL, CTXL, CCH, CCH,
                BATCH * HEADS, HEADS,
                (long long)HEADS * HW * CTXL, (long long)HW * CTXL,
                (long long)CTXL * CCH, DH,
                (long long)HW * CCH, DH, 1.f);
    launch_gemm(false, ao, wo2, bo2, t, t, MTOK, CCH, CCH, CCH, CCH, CCH,
                1, 1, 0, 0, 0, 0, 0, 0, 1.f);

    // ---- GEGLU FF ----
    layernorm_kernel<<<MTOK, 256>>>(t, ln3_s, ln3_b, tmp);
    launch_gemm(false, tmp, ff_w1, ff_b1, nullptr, ffh, MTOK, 2 * FFD, CCH,
                CCH, 2 * FFD, 2 * FFD, 1, 1, 0, 0, 0, 0, 0, 0, 1.f);
    {
        size_t total = (size_t)MTOK * FFD;
        geglu_kernel<<<(int)((total + 255) / 256), 256>>>(ffh, ffa);
    }
    launch_gemm(false, ffa, ff_w2, ff_b2, t, t, MTOK, CCH, FFD, FFD, CCH, CCH,
                1, 1, 0, 0, 0, 0, 0, 0, 1.f);

    // ---- proj_out + residual ----
    launch_gemm(false, t, pout_w, pout_b, nullptr, tmp, MTOK, CCH, CCH, CCH, CCH, CCH,
                1, 1, 0, 0, 0, 0, 0, 0, 1.f);
    {
        size_t total = (size_t)BATCH * CCH * HW;
        final_kernel<<<(int)((total + 255) / 256), 256>>>(tmp, x, out);
    }
}

// round 4
// speedup vs baseline: 2.3056x; 1.0700x over previous
#include <cuda_runtime.h>
#include <math.h>
#include <stdint.h>

// ---------------- problem constants ----------------
#define BATCH   2
#define CCH     1024
#define HW      1600
#define MTOK    (BATCH*HW)
#define HEADS   16
#define DH      64
#define CTXL    77
#define FFD     4096
#define GN_GROUPS 32
#define GN_EPS  1e-6f
#define LN_EPS  1e-5f

// ---------------- scratch ----------------
__device__ float g_t   [MTOK * CCH];
__device__ float g_tmp [MTOK * CCH];
__device__ float g_qkv [MTOK * 3 * CCH];
__device__ float g_ao  [MTOK * CCH];
__device__ float g_scores[(size_t)BATCH * HEADS * HW * HW];
__device__ float g_ffh [MTOK * 2 * FFD];
__device__ float g_ffa [MTOK * FFD];
__device__ float g_w3  [CCH * 3 * CCH];   // wq1|wk1|wv1
__device__ float g_w2c [CCH * 2 * CCH];   // wk2|wv2

// ---------------- reductions ----------------
__device__ __forceinline__ float blockReduceSum(float v) {
    __shared__ float sh[32];
    int lane = threadIdx.x & 31, wid = threadIdx.x >> 5;
#pragma unroll
    for (int o = 16; o > 0; o >>= 1) v += __shfl_down_sync(0xffffffffu, v, o);
    if (lane == 0) sh[wid] = v;
    __syncthreads();
    int nw = (blockDim.x + 31) >> 5;
    v = (threadIdx.x < nw) ? sh[threadIdx.x] : 0.f;
    if (wid == 0) {
#pragma unroll
        for (int o = 16; o > 0; o >>= 1) v += __shfl_down_sync(0xffffffffu, v, o);
        if (lane == 0) sh[0] = v;
    }
    __syncthreads();
    float r = sh[0];
    __syncthreads();
    return r;
}

__device__ __forceinline__ float blockReduceMax(float v) {
    __shared__ float sh[32];
    int lane = threadIdx.x & 31, wid = threadIdx.x >> 5;
#pragma unroll
    for (int o = 16; o > 0; o >>= 1) v = fmaxf(v, __shfl_down_sync(0xffffffffu, v, o));
    if (lane == 0) sh[wid] = v;
    __syncthreads();
    int nw = (blockDim.x + 31) >> 5;
    v = (threadIdx.x < nw) ? sh[threadIdx.x] : -INFINITY;
    if (wid == 0) {
#pragma unroll
        for (int o = 16; o > 0; o >>= 1) v = fmaxf(v, __shfl_down_sync(0xffffffffu, v, o));
        if (lane == 0) sh[0] = v;
    }
    __syncthreads();
    float r = sh[0];
    __syncthreads();
    return r;
}

// ---------------- GroupNorm + transpose ----------------
__global__ void groupnorm_kernel(const float* __restrict__ x,
                                 const float* __restrict__ s,
                                 const float* __restrict__ bgn,
                                 float* __restrict__ out) {
    int b = blockIdx.x / GN_GROUPS;
    int g = blockIdx.x % GN_GROUPS;
    const int CPG = CCH / GN_GROUPS;
    const int NEL = CPG * HW;
    const float* xp = x + ((size_t)b * CCH + (size_t)g * CPG) * HW;

    float sum = 0.f, sq = 0.f;
    for (int i = threadIdx.x; i < NEL; i += blockDim.x) {
        float v = xp[i];
        sum += v; sq += v * v;
    }
    sum = blockReduceSum(sum);
    sq  = blockReduceSum(sq);
    float mean = sum / (float)NEL;
    float var  = sq / (float)NEL - mean * mean;
    float inv  = rsqrtf(var + GN_EPS);

    for (int i = threadIdx.x; i < NEL; i += blockDim.x) {
        int ci = i / HW;
        int p  = i % HW;
        int c  = g * CPG + ci;
        float v = (xp[i] - mean) * inv * s[c] + bgn[c];
        out[((size_t)b * HW + p) * CCH + c] = v;
    }
}

// ---------------- LayerNorm ----------------
__global__ void layernorm_kernel(const float* __restrict__ x,
                                 const float* __restrict__ s,
                                 const float* __restrict__ b,
                                 float* __restrict__ out) {
    int row = blockIdx.x;
    const float* xr = x + (size_t)row * CCH;
    float sum = 0.f, sq = 0.f;
    for (int i = threadIdx.x; i < CCH; i += blockDim.x) {
        float v = xr[i];
        sum += v; sq += v * v;
    }
    sum = blockReduceSum(sum);
    sq  = blockReduceSum(sq);
    float mean = sum / (float)CCH;
    float var  = sq / (float)CCH - mean * mean;
    float inv  = rsqrtf(var + LN_EPS);
    float* o = out + (size_t)row * CCH;
    for (int i = threadIdx.x; i < CCH; i += blockDim.x)
        o[i] = (xr[i] - mean) * inv * s[i] + b[i];
}

// ---------------- tf32 helpers ----------------
__device__ __forceinline__ float f2tf32(float x) {
    uint32_t u;
    asm("cvt.rna.tf32.f32 %0, %1;" : "=r"(u) : "f"(x));
    return __uint_as_float(u);
}

__device__ __forceinline__ void mma_f4(float c[4], float4 a, float b0, float b1) {
    asm volatile(
        "mma.sync.aligned.m16n8k8.row.col.f32.tf32.tf32.f32 "
        "{%0,%1,%2,%3}, {%4,%5,%6,%7}, {%8,%9}, {%0,%1,%2,%3};"
        : "+f"(c[0]), "+f"(c[1]), "+f"(c[2]), "+f"(c[3])
        : "r"(__float_as_uint(a.x)), "r"(__float_as_uint(a.y)),
          "r"(__float_as_uint(a.z)), "r"(__float_as_uint(a.w)),
          "r"(__float_as_uint(b0)), "r"(__float_as_uint(b1)));
}

// ---------------- tf32 tensor-core batched GEMM, fragment-major smem --------
// Block tile 128 x NT, 8 warps (4x2), warp tile 32 x NT/2.
// TB=false: B(k,n)=Bm[k*ldb+n]; TB=true: B(k,n)=Bm[n*ldb+k].
template<bool TB, int NT>
__global__ __launch_bounds__(256)
void mma_gemm_kernel(const float* __restrict__ A, const float* __restrict__ Bm,
                     const float* __restrict__ bias, const float* __restrict__ res,
                     float* __restrict__ C,
                     int M, int N, int K, int lda, int ldb, int ldc,
                     long long sAo, long long sAi, long long sBo, long long sBi,
                     long long sCo, long long sCi, int inner, float alpha) {
    constexpr int NPT = NT / 16;
    constexpr int NPW = NT / 32;
    constexpr int NJ  = NT / 16;
    constexpr int NBU = NT / 16;

    int z  = blockIdx.z;
    int zo = z / inner, zi = z % inner;
    A  += (size_t)(zo * sAo + zi * sAi);
    Bm += (size_t)(zo * sBo + zi * sBi);
    long long coff = zo * sCo + zi * sCi;
    C += coff;
    if (res) res += coff;

    __shared__ float Asf[2][2][8][32][4];
    __shared__ float Bsf[2][2][NPT][32][4];

    const int tid  = threadIdx.x;
    const int wid  = tid >> 5;
    const int lane = tid & 31;
    const int wr   = wid >> 1;
    const int wc   = wid & 1;
    const int gp   = lane >> 2;
    const int tg   = lane & 3;
    const int mBase = blockIdx.y * 128;
    const int nBase = blockIdx.x * NT;

    float acc[2][NJ][4];
#pragma unroll
    for (int i = 0; i < 2; i++)
#pragma unroll
        for (int j = 0; j < NJ; j++)
#pragma unroll
            for (int q = 0; q < 4; q++) acc[i][j][q] = 0.f;

    float ra[8], rb[NBU];
    const int ktiles = (K + 15) / 16;

    auto loadRegs = [&](int kt) {
        const int k0 = kt * 16;
#pragma unroll
        for (int u = 0; u < 8; u++) {
            int e = u * 256 + tid;
            int row = e >> 4, kk = e & 15;
            int gm = mBase + row, gk = k0 + kk;
            ra[u] = (gm < M && gk < K) ? A[(size_t)gm * lda + gk] : 0.f;
        }
#pragma unroll
        for (int u = 0; u < NBU; u++) {
            int e = u * 256 + tid;
            int n, kk;
            if (TB) { n = e >> 4; kk = e & 15; }
            else    { kk = e / NT; n = e & (NT - 1); }
            int gk = k0 + kk, gn = nBase + n;
            rb[u] = (gk < K && gn < N)
                    ? (TB ? Bm[(size_t)gn * ldb + gk] : Bm[(size_t)gk * ldb + gn])
                    : 0.f;
        }
    };

    auto storeFrag = [&](int bf) {
#pragma unroll
        for (int u = 0; u < 8; u++) {
            int e = u * 256 + tid;
            int row = e >> 4, k = e & 15;
            int ln = ((row & 7) << 2) | (k & 3);
            int sl = ((row >> 3) & 1) | (((k >> 2) & 1) << 1);
            Asf[bf][k >> 3][row >> 4][ln][sl] = f2tf32(ra[u]);
        }
#pragma unroll
        for (int u = 0; u < NBU; u++) {
            int e = u * 256 + tid;
            int n, k;
            if (TB) { n = e >> 4; k = e & 15; }
            else    { k = e / NT; n = e & (NT - 1); }
            int ln = ((n & 7) << 2) | (k & 3);
            int sl = (((n >> 3) & 1) << 1) | ((k >> 2) & 1);
            Bsf[bf][k >> 3][n >> 4][ln][sl] = f2tf32(rb[u]);
        }
    };

    loadRegs(0);
    storeFrag(0);
    __syncthreads();

    for (int kt = 0; kt < ktiles; kt++) {
        int buf = kt & 1;
        if (kt + 1 < ktiles) loadRegs(kt + 1);

#pragma unroll
        for (int ks = 0; ks < 2; ks++) {
            float4 af[2];
#pragma unroll
            for (int i = 0; i < 2; i++)
                af[i] = *reinterpret_cast<const float4*>(&Asf[buf][ks][wr * 2 + i][lane][0]);
            float4 bf[NPW];
#pragma unroll
            for (int p = 0; p < NPW; p++)
                bf[p] = *reinterpret_cast<const float4*>(&Bsf[buf][ks][wc * NPW + p][lane][0]);
#pragma unroll
            for (int p = 0; p < NPW; p++) {
#pragma unroll
                for (int i = 0; i < 2; i++) {
                    mma_f4(acc[i][2 * p    ], af[i], bf[p].x, bf[p].y);
                    mma_f4(acc[i][2 * p + 1], af[i], bf[p].z, bf[p].w);
                }
            }
        }

        if (kt + 1 < ktiles) storeFrag((kt + 1) & 1);
        __syncthreads();
    }

    // ---- epilogue ----
    const bool evenLdc = ((ldc & 1) == 0);   // float2 path valid only then
#pragma unroll
    for (int i = 0; i < 2; i++) {
#pragma unroll
        for (int j = 0; j < NJ; j++) {
            int r0 = mBase + wr * 32 + i * 16 + gp;
            int c0 = nBase + wc * (NT / 2) + j * 8 + tg * 2;
#pragma unroll
            for (int h = 0; h < 2; h++) {
                int row = r0 + h * 8;
                if (row >= M) continue;
                float v0 = acc[i][j][h * 2 + 0] * alpha;
                float v1 = acc[i][j][h * 2 + 1] * alpha;
                if (evenLdc && c0 + 1 < N) {
                    if (bias) { v0 += bias[c0]; v1 += bias[c0 + 1]; }
                    if (res) {
                        const float2 rr = *reinterpret_cast<const float2*>(&res[(size_t)row * ldc + c0]);
                        v0 += rr.x; v1 += rr.y;
                    }
                    float2 o; o.x = v0; o.y = v1;
                    *reinterpret_cast<float2*>(&C[(size_t)row * ldc + c0]) = o;
                } else {
                    if (c0 < N) {
                        if (bias) v0 += bias[c0];
                        if (res)  v0 += res[(size_t)row * ldc + c0];
                        C[(size_t)row * ldc + c0] = v0;
                    }
                    if (c0 + 1 < N) {
                        if (bias) v1 += bias[c0 + 1];
                        if (res)  v1 += res[(size_t)row * ldc + c0 + 1];
                        C[(size_t)row * ldc + c0 + 1] = v1;
                    }
                }
            }
        }
    }
}

// ---------------- softmax (row cached in smem) ----------------
__global__ void softmax_kernel(float* __restrict__ sc, int len) {
    __shared__ float rowbuf[HW];
    float* p = sc + (size_t)blockIdx.x * len;
    float mx = -INFINITY;
    for (int i = threadIdx.x; i < len; i += blockDim.x) {
        float v = p[i];
        rowbuf[i] = v;
        mx = fmaxf(mx, v);
    }
    mx = blockReduceMax(mx);
    float sum = 0.f;
    for (int i = threadIdx.x; i < len; i += blockDim.x) {
        float e = __expf(rowbuf[i] - mx);
        rowbuf[i] = e;
        sum += e;
    }
    sum = blockReduceSum(sum);
    float inv = 1.f / sum;
    for (int i = threadIdx.x; i < len; i += blockDim.x)
        p[i] = rowbuf[i] * inv;
}

// ---------------- GEGLU ----------------
__global__ void geglu_kernel(const float* __restrict__ h, float* __restrict__ out) {
    size_t idx = (size_t)blockIdx.x * blockDim.x + threadIdx.x;
    size_t total = (size_t)MTOK * FFD;
    if (idx >= total) return;
    size_t row = idx / FFD;
    size_t col = idx % FFD;
    float a = h[row * (2 * FFD) + col];
    float g = h[row * (2 * FFD) + FFD + col];
    float gelu = 0.5f * g * (1.f + erff(g * 0.70710678118654752f));
    out[idx] = a * gelu;
}

// ---------------- final transpose + residual ----------------
__global__ void final_kernel(const float* __restrict__ proj,
                             const float* __restrict__ x,
                             float* __restrict__ out) {
    size_t idx = (size_t)blockIdx.x * blockDim.x + threadIdx.x;
    size_t total = (size_t)BATCH * CCH * HW;
    if (idx >= total) return;
    size_t p  = idx % HW;
    size_t bc = idx / HW;
    size_t c  = bc % CCH;
    size_t b  = bc / CCH;
    out[idx] = proj[((size_t)b * HW + p) * CCH + c] + x[idx];
}

// ---------------- host side ----------------
static void launch_gemm(bool tb, int nt, const float* A, const float* B,
                        const float* bias, const float* res, float* C,
                        int M, int N, int K, int lda, int ldb, int ldc,
                        int batches, int inner,
                        long long sAo, long long sAi, long long sBo, long long sBi,
                        long long sCo, long long sCi, float alpha) {
    dim3 grid((N + nt - 1) / nt, (M + 127) / 128, batches);
    dim3 block(256);
    if (tb) {
        if (nt == 128)
            mma_gemm_kernel<true, 128><<<grid, block>>>(A, B, bias, res, C, M, N, K, lda, ldb, ldc,
                                                        sAo, sAi, sBo, sBi, sCo, sCi, inner, alpha);
        else
            mma_gemm_kernel<true, 64><<<grid, block>>>(A, B, bias, res, C, M, N, K, lda, ldb, ldc,
                                                       sAo, sAi, sBo, sBi, sCo, sCi, inner, alpha);
    } else {
        if (nt == 128)
            mma_gemm_kernel<false, 128><<<grid, block>>>(A, B, bias, res, C, M, N, K, lda, ldb, ldc,
                                                         sAo, sAi, sBo, sBi, sCo, sCi, inner, alpha);
        else
            mma_gemm_kernel<false, 64><<<grid, block>>>(A, B, bias, res, C, M, N, K, lda, ldb, ldc,
                                                        sAo, sAi, sBo, sBi, sCo, sCi, inner, alpha);
    }
}

extern "C" void kernel_launch(void* const* d_in, const int* in_sizes, int n_in,
                              void* d_out, int out_size) {
    const float* x      = (const float*)d_in[0];
    const float* ctx    = (const float*)d_in[1];
    const float* gn_s   = (const float*)d_in[2];
    const float* gn_b   = (const float*)d_in[3];
    const float* pin_w  = (const float*)d_in[4];
    const float* pin_b  = (const float*)d_in[5];
    const float* ln1_s  = (const float*)d_in[6];
    const float* ln1_b  = (const float*)d_in[7];
    const float* wq1    = (const float*)d_in[8];
    const float* wk1    = (const float*)d_in[9];
    const float* wv1    = (const float*)d_in[10];
    const float* wo1    = (const float*)d_in[11];
    const float* bo1    = (const float*)d_in[12];
    const float* ln2_s  = (const float*)d_in[13];
    const float* ln2_b  = (const float*)d_in[14];
    const float* wq2    = (const float*)d_in[15];
    const float* wk2    = (const float*)d_in[16];
    const float* wv2    = (const float*)d_in[17];
    const float* wo2    = (const float*)d_in[18];
    const float* bo2    = (const float*)d_in[19];
    const float* ln3_s  = (const float*)d_in[20];
    const float* ln3_b  = (const float*)d_in[21];
    const float* ff_w1  = (const float*)d_in[22];
    const float* ff_b1  = (const float*)d_in[23];
    const float* ff_w2  = (const float*)d_in[24];
    const float* ff_b2  = (const float*)d_in[25];
    const float* pout_w = (const float*)d_in[26];
    const float* pout_b = (const float*)d_in[27];
    float* out = (float*)d_out;

    float *t, *tmp, *qkv, *ao, *scores, *ffh, *ffa, *w3, *w2c;
    cudaGetSymbolAddress((void**)&t,      g_t);
    cudaGetSymbolAddress((void**)&tmp,    g_tmp);
    cudaGetSymbolAddress((void**)&qkv,    g_qkv);
    cudaGetSymbolAddress((void**)&ao,     g_ao);
    cudaGetSymbolAddress((void**)&scores, g_scores);
    cudaGetSymbolAddress((void**)&ffh,    g_ffh);
    cudaGetSymbolAddress((void**)&ffa,    g_ffa);
    cudaGetSymbolAddress((void**)&w3,     g_w3);
    cudaGetSymbolAddress((void**)&w2c,    g_w2c);

    const float attn_scale = 0.125f;
    const int LD3 = 3 * CCH;
    const int LD2 = 2 * CCH;

    cudaMemcpy2DAsync(w3,         LD3 * 4, wq1, CCH * 4, CCH * 4, CCH, cudaMemcpyDeviceToDevice);
    cudaMemcpy2DAsync(w3 + CCH,   LD3 * 4, wk1, CCH * 4, CCH * 4, CCH, cudaMemcpyDeviceToDevice);
    cudaMemcpy2DAsync(w3 + 2*CCH, LD3 * 4, wv1, CCH * 4, CCH * 4, CCH, cudaMemcpyDeviceToDevice);
    cudaMemcpy2DAsync(w2c,        LD2 * 4, wk2, CCH * 4, CCH * 4, CCH, cudaMemcpyDeviceToDevice);
    cudaMemcpy2DAsync(w2c + CCH,  LD2 * 4, wv2, CCH * 4, CCH * 4, CCH, cudaMemcpyDeviceToDevice);

    groupnorm_kernel<<<BATCH * GN_GROUPS, 256>>>(x, gn_s, gn_b, tmp);

    launch_gemm(false, 128, tmp, pin_w, pin_b, nullptr, t, MTOK, CCH, CCH, CCH, CCH, CCH,
                1, 1, 0, 0, 0, 0, 0, 0, 1.f);

    // ---- self-attention ----
    layernorm_kernel<<<MTOK, 256>>>(t, ln1_s, ln1_b, tmp);
    launch_gemm(false, 128, tmp, w3, nullptr, nullptr, qkv, MTOK, 3 * CCH, CCH,
                CCH, LD3, LD3, 1, 1, 0, 0, 0, 0, 0, 0, 1.f);
    launch_gemm(true, 128, qkv, qkv + CCH, nullptr, nullptr, scores, HW, HW, DH,
                LD3, LD3, HW, BATCH * HEADS, HEADS,
                (long long)HW * LD3, DH, (long long)HW * LD3, DH,
                (long long)HEADS * HW * HW, (long long)HW * HW, attn_scale);
    softmax_kernel<<<BATCH * HEADS * HW, 256>>>(scores, HW);
    launch_gemm(false, 64, scores, qkv + 2 * CCH, nullptr, nullptr, ao, HW, DH, HW,
                HW, LD3, CCH, BATCH * HEADS, HEADS,
                (long long)HEADS * HW * HW, (long long)HW * HW,
                (long long)HW * LD3, DH,
                (long long)HW * CCH, DH, 1.f);
    launch_gemm(false, 128, ao, wo1, bo1, t, t, MTOK, CCH, CCH, CCH, CCH, CCH,
                1, 1, 0, 0, 0, 0, 0, 0, 1.f);

    // ---- cross-attention ----
    layernorm_kernel<<<MTOK, 256>>>(t, ln2_s, ln2_b, tmp);
    launch_gemm(false, 128, tmp, wq2, nullptr, nullptr, qkv, MTOK, CCH, CCH,
                CCH, CCH, LD3, 1, 1, 0, 0, 0, 0, 0, 0, 1.f);
    launch_gemm(false, 128, ctx, w2c, nullptr, nullptr, qkv + CCH, BATCH * CTXL, 2 * CCH, CCH,
                CCH, LD2, LD3, 1, 1, 0, 0, 0, 0, 0, 0, 1.f);
    launch_gemm(true, 64, qkv, qkv + CCH, nullptr, nullptr, scores, HW, CTXL, DH,
                LD3, LD3, CTXL, BATCH * HEADS, HEADS,
                (long long)HW * LD3, DH, (long long)CTXL * LD3, DH,
                (long long)HEADS * HW * CTXL, (long long)HW * CTXL, attn_scale);
    softmax_kernel<<<BATCH * HEADS * HW, 256>>>(scores, CTXL);
    launch_gemm(false, 64, scores, qkv + 2 * CCH, nullptr, nullptr, ao, HW, DH, CTXL,
                CTXL, LD3, CCH, BATCH * HEADS, HEADS,
                (long long)HEADS * HW * CTXL, (long long)HW * CTXL,
                (long long)CTXL * LD3, DH,
                (long long)HW * CCH, DH, 1.f);
    launch_gemm(false, 128, ao, wo2, bo2, t, t, MTOK, CCH, CCH, CCH, CCH, CCH,
                1, 1, 0, 0, 0, 0, 0, 0, 1.f);

    // ---- GEGLU FF ----
    layernorm_kernel<<<MTOK, 256>>>(t, ln3_s, ln3_b, tmp);
    launch_gemm(false, 128, tmp, ff_w1, ff_b1, nullptr, ffh, MTOK, 2 * FFD, CCH,
                CCH, 2 * FFD, 2 * FFD, 1, 1, 0, 0, 0, 0, 0, 0, 1.f);
    {
        size_t total = (size_t)MTOK * FFD;
        geglu_kernel<<<(int)((total + 255) / 256), 256>>>(ffh, ffa);
    }
    launch_gemm(false, 128, ffa, ff_w2, ff_b2, t, t, MTOK, CCH, FFD, FFD, CCH, CCH,
                1, 1, 0, 0, 0, 0, 0, 0, 1.f);

    // ---- proj_out + residual ----
    launch_gemm(false, 128, t, pout_w, pout_b, nullptr, tmp, MTOK, CCH, CCH, CCH, CCH, CCH,
                1, 1, 0, 0, 0, 0, 0, 0, 1.f);
    {
        size_t total = (size_t)BATCH * CCH * HW;
        final_kernel<<<(int)((total + 255) / 256), 256>>>(tmp, x, out);
    }
}

// round 6
// speedup vs baseline: 2.9609x; 1.2842x over previous
#include <cuda_runtime.h>
#include <math.h>
#include <stdint.h>

// ---------------- problem constants ----------------
#define BATCH   2
#define CCH     1024
#define HW      1600
#define MTOK    (BATCH*HW)
#define HEADS   16
#define DH      64
#define CTXL    77
#define CTXP    80          // padded ld for cross-attn scores
#define FFD     4096
#define GN_GROUPS 32
#define GN_EPS  1e-6f
#define LN_EPS  1e-5f

// ---------------- scratch ----------------
__device__ float g_t   [MTOK * CCH];
__device__ float g_tmp [MTOK * CCH];
__device__ float g_qkv [MTOK * 3 * CCH];
__device__ float g_ao  [MTOK * CCH];
__device__ float g_scores[(size_t)BATCH * HEADS * HW * HW];
__device__ float g_ffh [MTOK * 2 * FFD];
__device__ float g_ffa [MTOK * FFD];
__device__ float g_w3  [CCH * 3 * CCH];
__device__ float g_w2c [CCH * 2 * CCH];

// ---------------- reductions ----------------
__device__ __forceinline__ float blockReduceSum(float v) {
    __shared__ float sh[32];
    int lane = threadIdx.x & 31, wid = threadIdx.x >> 5;
#pragma unroll
    for (int o = 16; o > 0; o >>= 1) v += __shfl_down_sync(0xffffffffu, v, o);
    if (lane == 0) sh[wid] = v;
    __syncthreads();
    int nw = (blockDim.x + 31) >> 5;
    v = (threadIdx.x < nw) ? sh[threadIdx.x] : 0.f;
    if (wid == 0) {
#pragma unroll
        for (int o = 16; o > 0; o >>= 1) v += __shfl_down_sync(0xffffffffu, v, o);
        if (lane == 0) sh[0] = v;
    }
    __syncthreads();
    float r = sh[0];
    __syncthreads();
    return r;
}

__device__ __forceinline__ float blockReduceMax(float v) {
    __shared__ float sh[32];
    int lane = threadIdx.x & 31, wid = threadIdx.x >> 5;
#pragma unroll
    for (int o = 16; o > 0; o >>= 1) v = fmaxf(v, __shfl_down_sync(0xffffffffu, v, o));
    if (lane == 0) sh[wid] = v;
    __syncthreads();
    int nw = (blockDim.x + 31) >> 5;
    v = (threadIdx.x < nw) ? sh[threadIdx.x] : -INFINITY;
    if (wid == 0) {
#pragma unroll
        for (int o = 16; o > 0; o >>= 1) v = fmaxf(v, __shfl_down_sync(0xffffffffu, v, o));
        if (lane == 0) sh[0] = v;
    }
    __syncthreads();
    float r = sh[0];
    __syncthreads();
    return r;
}

// ---------------- GroupNorm + transpose ----------------
__global__ void groupnorm_kernel(const float* __restrict__ x,
                                 const float* __restrict__ s,
                                 const float* __restrict__ bgn,
                                 float* __restrict__ out) {
    int b = blockIdx.x / GN_GROUPS;
    int g = blockIdx.x % GN_GROUPS;
    const int CPG = CCH / GN_GROUPS;
    const int NEL = CPG * HW;
    const float* xp = x + ((size_t)b * CCH + (size_t)g * CPG) * HW;

    float sum = 0.f, sq = 0.f;
    for (int i = threadIdx.x; i < NEL; i += blockDim.x) {
        float v = xp[i];
        sum += v; sq += v * v;
    }
    sum = blockReduceSum(sum);
    sq  = blockReduceSum(sq);
    float mean = sum / (float)NEL;
    float var  = sq / (float)NEL - mean * mean;
    float inv  = rsqrtf(var + GN_EPS);

    for (int i = threadIdx.x; i < NEL; i += blockDim.x) {
        int ci = i / HW;
        int p  = i % HW;
        int c  = g * CPG + ci;
        float v = (xp[i] - mean) * inv * s[c] + bgn[c];
        out[((size_t)b * HW + p) * CCH + c] = v;
    }
}

// ---------------- LayerNorm ----------------
__global__ void layernorm_kernel(const float* __restrict__ x,
                                 const float* __restrict__ s,
                                 const float* __restrict__ b,
                                 float* __restrict__ out) {
    int row = blockIdx.x;
    const float* xr = x + (size_t)row * CCH;
    float sum = 0.f, sq = 0.f;
    for (int i = threadIdx.x; i < CCH; i += blockDim.x) {
        float v = xr[i];
        sum += v; sq += v * v;
    }
    sum = blockReduceSum(sum);
    sq  = blockReduceSum(sq);
    float mean = sum / (float)CCH;
    float var  = sq / (float)CCH - mean * mean;
    float inv  = rsqrtf(var + LN_EPS);
    float* o = out + (size_t)row * CCH;
    for (int i = threadIdx.x; i < CCH; i += blockDim.x)
        o[i] = (xr[i] - mean) * inv * s[i] + b[i];
}

// ---------------- tf32 helpers ----------------
__device__ __forceinline__ float f2tf32(float x) {
    uint32_t u;
    asm("cvt.rna.tf32.f32 %0, %1;" : "=r"(u) : "f"(x));
    return __uint_as_float(u);
}

__device__ __forceinline__ void mma4(float c[4], const float a[4], float b0, float b1) {
    asm volatile(
        "mma.sync.aligned.m16n8k8.row.col.f32.tf32.tf32.f32 "
        "{%0,%1,%2,%3}, {%4,%5,%6,%7}, {%8,%9}, {%0,%1,%2,%3};"
        : "+f"(c[0]), "+f"(c[1]), "+f"(c[2]), "+f"(c[3])
        : "r"(__float_as_uint(a[0])), "r"(__float_as_uint(a[1])),
          "r"(__float_as_uint(a[2])), "r"(__float_as_uint(a[3])),
          "r"(__float_as_uint(b0)), "r"(__float_as_uint(b1)));
}

// ---------------- tf32 tensor-core batched GEMM ----------------
// 128 x NT block tile, 8 warps (4x2), fragment-major smem.
// Requires: K % 16 == 0, lda % 4 == 0, ldb % 4 == 0, 16B-aligned A/B bases.
// TB=false: B(k,n)=Bm[k*ldb+n] (block n-range fully in bounds);
// TB=true:  B(k,n)=Bm[n*ldb+k].
template<bool TB, int NT>
__global__ __launch_bounds__(256)
void mma_gemm_kernel(const float* __restrict__ A, const float* __restrict__ Bm,
                     const float* __restrict__ bias, const float* __restrict__ res,
                     float* __restrict__ C,
                     int M, int N, int K, int lda, int ldb, int ldc,
                     long long sAo, long long sAi, long long sBo, long long sBi,
                     long long sCo, long long sCi, int inner, float alpha) {
    constexpr int NPW = NT / 32;
    constexpr int NJ  = NT / 16;
    constexpr int ASZ = 8 * 264;
    constexpr int BSZ = (NT / 16) * 264;
    constexpr int NB4 = (NT == 128) ? 2 : 1;

    int z  = blockIdx.z;
    int zo = z / inner, zi = z % inner;
    A  += (size_t)(zo * sAo + zi * sAi);
    Bm += (size_t)(zo * sBo + zi * sBi);
    long long coff = zo * sCo + zi * sCi;
    C += coff;
    if (res) res += coff;

    __shared__ float SA[2 * ASZ];
    __shared__ float SB[2 * BSZ];

    const int tid  = threadIdx.x;
    const int wid  = tid >> 5;
    const int lane = tid & 31;
    const int wr   = wid >> 1;
    const int wc   = wid & 1;
    const int gp   = lane >> 2;
    const int tg   = lane & 3;
    const int mBase = blockIdx.y * 128;
    const int nBase = blockIdx.x * NT;

    // ---- precompute A staging (loop-invariant) ----
    const float4* pA[2];
    int ofA[2];
#pragma unroll
    for (int u = 0; u < 2; u++) {
        int e = u * 256 + tid;
        int row = e >> 2, kq = e & 3;
        int gm = mBase + row;
        if (gm >= M) gm = 0;   // clamp: garbage lands in dead acc cells
        pA[u] = reinterpret_cast<const float4*>(A + (size_t)gm * lda) + kq;
        int sl = ((row >> 3) & 1) | ((kq & 1) << 1);
        ofA[u] = (row >> 4) * 264 + sl * 66 + (kq >> 1) * 33 + ((row & 7) << 2);
    }

    // ---- precompute B staging ----
    const float4* pB[NB4];
    int ofB[NB4];
#pragma unroll
    for (int u = 0; u < NB4; u++) {
        int e = u * 256 + tid;
        if (TB) {
            int n = e >> 2, kq = e & 3;
            int gn = nBase + n;
            if (gn >= N) gn = 0;
            pB[u] = reinterpret_cast<const float4*>(Bm + (size_t)gn * ldb) + kq;
            int sl = (((n >> 3) & 1) << 1) | (kq & 1);
            ofB[u] = (n >> 4) * 264 + sl * 66 + (kq >> 1) * 33 + ((n & 7) << 2);
        } else {
            int k, nq;
            if (NT == 128) { k = e >> 5; nq = e & 31; }
            else           { k = e >> 4; nq = e & 15; }
            pB[u] = reinterpret_cast<const float4*>(Bm + (size_t)k * ldb + nBase) + nq;
            int sl = (((nq >> 1) & 1) << 1) | ((k >> 2) & 1);
            ofB[u] = (nq >> 2) * 264 + sl * 66 + (k >> 3) * 33 + ((nq & 1) << 4) + (k & 3);
        }
    }
    // float4 step per 16-row k-tile:
    //   TB: 16 floats along contiguous k  -> 4 float4
    //   !TB: 16 rows of ldb floats        -> 4*ldb float4   (round-5 bug: was ldb)
    const long long stepB = TB ? 4LL : 4LL * (long long)ldb;

    float acc[2][NJ][4];
#pragma unroll
    for (int i = 0; i < 2; i++)
#pragma unroll
        for (int j = 0; j < NJ; j++)
#pragma unroll
            for (int q = 0; q < 4; q++) acc[i][j][q] = 0.f;

    float4 va[2], vb[NB4];

    auto loadTile = [&]() {
#pragma unroll
        for (int u = 0; u < 2; u++) { va[u] = *pA[u]; pA[u] += 4; }
#pragma unroll
        for (int u = 0; u < NB4; u++) { vb[u] = *pB[u]; pB[u] += stepB; }
    };
    auto storeTile = [&](int bf) {
        float* sa = SA + bf * ASZ;
        float* sb = SB + bf * BSZ;
#pragma unroll
        for (int u = 0; u < 2; u++) {
            sa[ofA[u] + 0] = f2tf32(va[u].x);
            sa[ofA[u] + 1] = f2tf32(va[u].y);
            sa[ofA[u] + 2] = f2tf32(va[u].z);
            sa[ofA[u] + 3] = f2tf32(va[u].w);
        }
#pragma unroll
        for (int u = 0; u < NB4; u++) {
            if (TB) {
                sb[ofB[u] + 0] = f2tf32(vb[u].x);
                sb[ofB[u] + 1] = f2tf32(vb[u].y);
                sb[ofB[u] + 2] = f2tf32(vb[u].z);
                sb[ofB[u] + 3] = f2tf32(vb[u].w);
            } else {
                sb[ofB[u] + 0]  = f2tf32(vb[u].x);
                sb[ofB[u] + 4]  = f2tf32(vb[u].y);
                sb[ofB[u] + 8]  = f2tf32(vb[u].z);
                sb[ofB[u] + 12] = f2tf32(vb[u].w);
            }
        }
    };

    loadTile();
    storeTile(0);
    __syncthreads();

    const int ktiles = K >> 4;
    const int aB = wr * 2 * 264 + lane;
    const int bB = wc * NPW * 264 + lane;

    for (int kt = 0; kt < ktiles; kt++) {
        const float* sa = SA + (kt & 1) * ASZ;
        const float* sb = SB + (kt & 1) * BSZ;
        bool more = (kt + 1 < ktiles);
        if (more) loadTile();

#pragma unroll
        for (int ks = 0; ks < 2; ks++) {
            float a0[4], a1[4];
#pragma unroll
            for (int s = 0; s < 4; s++) {
                a0[s] = sa[aB +       s * 66 + ks * 33];
                a1[s] = sa[aB + 264 + s * 66 + ks * 33];
            }
#pragma unroll
            for (int p = 0; p < NPW; p++) {
                float bb[4];
#pragma unroll
                for (int s = 0; s < 4; s++)
                    bb[s] = sb[bB + p * 264 + s * 66 + ks * 33];
                mma4(acc[0][2 * p    ], a0, bb[0], bb[1]);
                mma4(acc[1][2 * p    ], a1, bb[0], bb[1]);
                mma4(acc[0][2 * p + 1], a0, bb[2], bb[3]);
                mma4(acc[1][2 * p + 1], a1, bb[2], bb[3]);
            }
        }

        if (more) storeTile((kt + 1) & 1);
        __syncthreads();
    }

    // ---- epilogue ----
    const bool evenLdc = ((ldc & 1) == 0);
#pragma unroll
    for (int i = 0; i < 2; i++) {
#pragma unroll
        for (int j = 0; j < NJ; j++) {
            int r0 = mBase + wr * 32 + i * 16 + gp;
            int c0 = nBase + wc * (NT / 2) + j * 8 + tg * 2;
#pragma unroll
            for (int h = 0; h < 2; h++) {
                int row = r0 + h * 8;
                if (row >= M) continue;
                float v0 = acc[i][j][h * 2 + 0] * alpha;
                float v1 = acc[i][j][h * 2 + 1] * alpha;
                if (evenLdc && c0 + 1 < N) {
                    if (bias) { v0 += bias[c0]; v1 += bias[c0 + 1]; }
                    if (res) {
                        const float2 rr = *reinterpret_cast<const float2*>(&res[(size_t)row * ldc + c0]);
                        v0 += rr.x; v1 += rr.y;
                    }
                    float2 o; o.x = v0; o.y = v1;
                    *reinterpret_cast<float2*>(&C[(size_t)row * ldc + c0]) = o;
                } else {
                    if (c0 < N) {
                        if (bias) v0 += bias[c0];
                        if (res)  v0 += res[(size_t)row * ldc + c0];
                        C[(size_t)row * ldc + c0] = v0;
                    }
                    if (c0 + 1 < N) {
                        if (bias) v1 += bias[c0 + 1];
                        if (res)  v1 += res[(size_t)row * ldc + c0 + 1];
                        C[(size_t)row * ldc + c0 + 1] = v1;
                    }
                }
            }
        }
    }
}

// ---------------- softmax (row cached in smem, optional zero-pad) ----------
__global__ void softmax_kernel(float* __restrict__ sc, int len, int ld, int pad) {
    __shared__ float rowbuf[HW];
    float* p = sc + (size_t)blockIdx.x * ld;
    float mx = -INFINITY;
    for (int i = threadIdx.x; i < len; i += blockDim.x) {
        float v = p[i];
        rowbuf[i] = v;
        mx = fmaxf(mx, v);
    }
    mx = blockReduceMax(mx);
    float sum = 0.f;
    for (int i = threadIdx.x; i < len; i += blockDim.x) {
        float e = __expf(rowbuf[i] - mx);
        rowbuf[i] = e;
        sum += e;
    }
    sum = blockReduceSum(sum);
    float inv = 1.f / sum;
    for (int i = threadIdx.x; i < len; i += blockDim.x)
        p[i] = rowbuf[i] * inv;
    for (int i = len + threadIdx.x; i < pad; i += blockDim.x)
        p[i] = 0.f;
}

// ---------------- GEGLU ----------------
__global__ void geglu_kernel(const float* __restrict__ h, float* __restrict__ out) {
    size_t idx = (size_t)blockIdx.x * blockDim.x + threadIdx.x;
    size_t total = (size_t)MTOK * FFD;
    if (idx >= total) return;
    size_t row = idx / FFD;
    size_t col = idx % FFD;
    float a = h[row * (2 * FFD) + col];
    float g = h[row * (2 * FFD) + FFD + col];
    float gelu = 0.5f * g * (1.f + erff(g * 0.70710678118654752f));
    out[idx] = a * gelu;
}

// ---------------- final transpose + residual ----------------
__global__ void final_kernel(const float* __restrict__ proj,
                             const float* __restrict__ x,
                             float* __restrict__ out) {
    size_t idx = (size_t)blockIdx.x * blockDim.x + threadIdx.x;
    size_t total = (size_t)BATCH * CCH * HW;
    if (idx >= total) return;
    size_t p  = idx % HW;
    size_t bc = idx / HW;
    size_t c  = bc % CCH;
    size_t b  = bc / CCH;
    out[idx] = proj[((size_t)b * HW + p) * CCH + c] + x[idx];
}

// ---------------- host side ----------------
static void launch_gemm(bool tb, int nt, const float* A, const float* B,
                        const float* bias, const float* res, float* C,
                        int M, int N, int K, int lda, int ldb, int ldc,
                        int batches, int inner,
                        long long sAo, long long sAi, long long sBo, long long sBi,
                        long long sCo, long long sCi, float alpha) {
    dim3 grid((N + nt - 1) / nt, (M + 127) / 128, batches);
    dim3 block(256);
    if (tb) {
        if (nt == 128)
            mma_gemm_kernel<true, 128><<<grid, block>>>(A, B, bias, res, C, M, N, K, lda, ldb, ldc,
                                                        sAo, sAi, sBo, sBi, sCo, sCi, inner, alpha);
        else
            mma_gemm_kernel<true, 64><<<grid, block>>>(A, B, bias, res, C, M, N, K, lda, ldb, ldc,
                                                       sAo, sAi, sBo, sBi, sCo, sCi, inner, alpha);
    } else {
        if (nt == 128)
            mma_gemm_kernel<false, 128><<<grid, block>>>(A, B, bias, res, C, M, N, K, lda, ldb, ldc,
                                                         sAo, sAi, sBo, sBi, sCo, sCi, inner, alpha);
        else
            mma_gemm_kernel<false, 64><<<grid, block>>>(A, B, bias, res, C, M, N, K, lda, ldb, ldc,
                                                        sAo, sAi, sBo, sBi, sCo, sCi, inner, alpha);
    }
}

extern "C" void kernel_launch(void* const* d_in, const int* in_sizes, int n_in,
                              void* d_out, int out_size) {
    const float* x      = (const float*)d_in[0];
    const float* ctx    = (const float*)d_in[1];
    const float* gn_s   = (const float*)d_in[2];
    const float* gn_b   = (const float*)d_in[3];
    const float* pin_w  = (const float*)d_in[4];
    const float* pin_b  = (const float*)d_in[5];
    const float* ln1_s  = (const float*)d_in[6];
    const float* ln1_b  = (const float*)d_in[7];
    const float* wq1    = (const float*)d_in[8];
    const float* wk1    = (const float*)d_in[9];
    const float* wv1    = (const float*)d_in[10];
    const float* wo1    = (const float*)d_in[11];
    const float* bo1    = (const float*)d_in[12];
    const float* ln2_s  = (const float*)d_in[13];
    const float* ln2_b  = (const float*)d_in[14];
    const float* wq2    = (const float*)d_in[15];
    const float* wk2    = (const float*)d_in[16];
    const float* wv2    = (const float*)d_in[17];
    const float* wo2    = (const float*)d_in[18];
    const float* bo2    = (const float*)d_in[19];
    const float* ln3_s  = (const float*)d_in[20];
    const float* ln3_b  = (const float*)d_in[21];
    const float* ff_w1  = (const float*)d_in[22];
    const float* ff_b1  = (const float*)d_in[23];
    const float* ff_w2  = (const float*)d_in[24];
    const float* ff_b2  = (const float*)d_in[25];
    const float* pout_w = (const float*)d_in[26];
    const float* pout_b = (const float*)d_in[27];
    float* out = (float*)d_out;

    float *t, *tmp, *qkv, *ao, *scores, *ffh, *ffa, *w3, *w2c;
    cudaGetSymbolAddress((void**)&t,      g_t);
    cudaGetSymbolAddress((void**)&tmp,    g_tmp);
    cudaGetSymbolAddress((void**)&qkv,    g_qkv);
    cudaGetSymbolAddress((void**)&ao,     g_ao);
    cudaGetSymbolAddress((void**)&scores, g_scores);
    cudaGetSymbolAddress((void**)&ffh,    g_ffh);
    cudaGetSymbolAddress((void**)&ffa,    g_ffa);
    cudaGetSymbolAddress((void**)&w3,     g_w3);
    cudaGetSymbolAddress((void**)&w2c,    g_w2c);

    const float attn_scale = 0.125f;
    const int LD3 = 3 * CCH;
    const int LD2 = 2 * CCH;

    cudaMemcpy2DAsync(w3,         LD3 * 4, wq1, CCH * 4, CCH * 4, CCH, cudaMemcpyDeviceToDevice);
    cudaMemcpy2DAsync(w3 + CCH,   LD3 * 4, wk1, CCH * 4, CCH * 4, CCH, cudaMemcpyDeviceToDevice);
    cudaMemcpy2DAsync(w3 + 2*CCH, LD3 * 4, wv1, CCH * 4, CCH * 4, CCH, cudaMemcpyDeviceToDevice);
    cudaMemcpy2DAsync(w2c,        LD2 * 4, wk2, CCH * 4, CCH * 4, CCH, cudaMemcpyDeviceToDevice);
    cudaMemcpy2DAsync(w2c + CCH,  LD2 * 4, wv2, CCH * 4, CCH * 4, CCH, cudaMemcpyDeviceToDevice);

    groupnorm_kernel<<<BATCH * GN_GROUPS, 256>>>(x, gn_s, gn_b, tmp);

    launch_gemm(false, 128, tmp, pin_w, pin_b, nullptr, t, MTOK, CCH, CCH, CCH, CCH, CCH,
                1, 1, 0, 0, 0, 0, 0, 0, 1.f);

    // ---- self-attention ----
    layernorm_kernel<<<MTOK, 256>>>(t, ln1_s, ln1_b, tmp);
    launch_gemm(false, 128, tmp, w3, nullptr, nullptr, qkv, MTOK, 3 * CCH, CCH,
                CCH, LD3, LD3, 1, 1, 0, 0, 0, 0, 0, 0, 1.f);
    launch_gemm(true, 128, qkv, qkv + CCH, nullptr, nullptr, scores, HW, HW, DH,
                LD3, LD3, HW, BATCH * HEADS, HEADS,
                (long long)HW * LD3, DH, (long long)HW * LD3, DH,
                (long long)HEADS * HW * HW, (long long)HW * HW, attn_scale);
    softmax_kernel<<<BATCH * HEADS * HW, 256>>>(scores, HW, HW, HW);
    launch_gemm(false, 64, scores, qkv + 2 * CCH, nullptr, nullptr, ao, HW, DH, HW,
                HW, LD3, CCH, BATCH * HEADS, HEADS,
                (long long)HEADS * HW * HW, (long long)HW * HW,
                (long long)HW * LD3, DH,
                (long long)HW * CCH, DH, 1.f);
    launch_gemm(false, 128, ao, wo1, bo1, t, t, MTOK, CCH, CCH, CCH, CCH, CCH,
                1, 1, 0, 0, 0, 0, 0, 0, 1.f);

    // ---- cross-attention (scores padded to ld=CTXP) ----
    layernorm_kernel<<<MTOK, 256>>>(t, ln2_s, ln2_b, tmp);
    launch_gemm(false, 128, tmp, wq2, nullptr, nullptr, qkv, MTOK, CCH, CCH,
                CCH, CCH, LD3, 1, 1, 0, 0, 0, 0, 0, 0, 1.f);
    launch_gemm(false, 128, ctx, w2c, nullptr, nullptr, qkv + CCH, BATCH * CTXL, 2 * CCH, CCH,
                CCH, LD2, LD3, 1, 1, 0, 0, 0, 0, 0, 0, 1.f);
    launch_gemm(true, 64, qkv, qkv + CCH, nullptr, nullptr, scores, HW, CTXL, DH,
                LD3, LD3, CTXP, BATCH * HEADS, HEADS,
                (long long)HW * LD3, DH, (long long)CTXL * LD3, DH,
                (long long)HEADS * HW * CTXP, (long long)HW * CTXP, attn_scale);
    softmax_kernel<<<BATCH * HEADS * HW, 256>>>(scores, CTXL, CTXP, CTXP);
    // K padded to CTXP=80 — pad score cols are zero, so extra V rows are inert
    launch_gemm(false, 64, scores, qkv + 2 * CCH, nullptr, nullptr, ao, HW, DH, CTXP,
                CTXP, LD3, CCH, BATCH * HEADS, HEADS,
                (long long)HEADS * HW * CTXP, (long long)HW * CTXP,
                (long long)CTXL * LD3, DH,
                (long long)HW * CCH, DH, 1.f);
    launch_gemm(false, 128, ao, wo2, bo2, t, t, MTOK, CCH, CCH, CCH, CCH, CCH,
                1, 1, 0, 0, 0, 0, 0, 0, 1.f);

    // ---- GEGLU FF ----
    layernorm_kernel<<<MTOK, 256>>>(t, ln3_s, ln3_b, tmp);
    launch_gemm(false, 128, tmp, ff_w1, ff_b1, nullptr, ffh, MTOK, 2 * FFD, CCH,
                CCH, 2 * FFD, 2 * FFD, 1, 1, 0, 0, 0, 0, 0, 0, 1.f);
    {
        size_t total = (size_t)MTOK * FFD;
        geglu_kernel<<<(int)((total + 255) / 256), 256>>>(ffh, ffa);
    }
    launch_gemm(false, 128, ffa, ff_w2, ff_b2, t, t, MTOK, CCH, FFD, FFD, CCH, CCH,
                1, 1, 0, 0, 0, 0, 0, 0, 1.f);

    // ---- proj_out + residual ----
    launch_gemm(false, 128, t, pout_w, pout_b, nullptr, tmp, MTOK, CCH, CCH, CCH, CCH, CCH,
                1, 1, 0, 0, 0, 0, 0, 0, 1.f);
    {
        size_t total = (size_t)BATCH * CCH * HW;
        final_kernel<<<(int)((total + 255) / 256), 256>>>(tmp, x, out);
    }
}

// round 7
// speedup vs baseline: 2.9712x; 1.0035x over previous
#include <cuda_runtime.h>
#include <math.h>
#include <stdint.h>

// ---------------- problem constants ----------------
#define BATCH   2
#define CCH     1024
#define HW      1600
#define MTOK    (BATCH*HW)
#define HEADS   16
#define DH      64
#define CTXL    77
#define CTXP    80          // padded ld for cross-attn scores
#define FFD     4096
#define GN_GROUPS 32
#define GN_EPS  1e-6f
#define LN_EPS  1e-5f

// ---------------- scratch ----------------
__device__ float g_t   [MTOK * CCH];
__device__ float g_tmp [MTOK * CCH];
__device__ float g_qkv [MTOK * 3 * CCH];
__device__ float g_ao  [MTOK * CCH];
__device__ float g_scores[(size_t)BATCH * HEADS * HW * HW];
__device__ float g_ffh [MTOK * 2 * FFD];
__device__ float g_ffa [MTOK * FFD];
__device__ float g_w3  [CCH * 3 * CCH];
__device__ float g_w2c [CCH * 2 * CCH];

// ---------------- reductions ----------------
__device__ __forceinline__ float blockReduceSum(float v) {
    __shared__ float sh[32];
    int lane = threadIdx.x & 31, wid = threadIdx.x >> 5;
#pragma unroll
    for (int o = 16; o > 0; o >>= 1) v += __shfl_down_sync(0xffffffffu, v, o);
    if (lane == 0) sh[wid] = v;
    __syncthreads();
    int nw = (blockDim.x + 31) >> 5;
    v = (threadIdx.x < nw) ? sh[threadIdx.x] : 0.f;
    if (wid == 0) {
#pragma unroll
        for (int o = 16; o > 0; o >>= 1) v += __shfl_down_sync(0xffffffffu, v, o);
        if (lane == 0) sh[0] = v;
    }
    __syncthreads();
    float r = sh[0];
    __syncthreads();
    return r;
}

__device__ __forceinline__ float blockReduceMax(float v) {
    __shared__ float sh[32];
    int lane = threadIdx.x & 31, wid = threadIdx.x >> 5;
#pragma unroll
    for (int o = 16; o > 0; o >>= 1) v = fmaxf(v, __shfl_down_sync(0xffffffffu, v, o));
    if (lane == 0) sh[wid] = v;
    __syncthreads();
    int nw = (blockDim.x + 31) >> 5;
    v = (threadIdx.x < nw) ? sh[threadIdx.x] : -INFINITY;
    if (wid == 0) {
#pragma unroll
        for (int o = 16; o > 0; o >>= 1) v = fmaxf(v, __shfl_down_sync(0xffffffffu, v, o));
        if (lane == 0) sh[0] = v;
    }
    __syncthreads();
    float r = sh[0];
    __syncthreads();
    return r;
}

// ---------------- GroupNorm + transpose ----------------
__global__ void groupnorm_kernel(const float* __restrict__ x,
                                 const float* __restrict__ s,
                                 const float* __restrict__ bgn,
                                 float* __restrict__ out) {
    int b = blockIdx.x / GN_GROUPS;
    int g = blockIdx.x % GN_GROUPS;
    const int CPG = CCH / GN_GROUPS;
    const int NEL = CPG * HW;
    const float* xp = x + ((size_t)b * CCH + (size_t)g * CPG) * HW;

    float sum = 0.f, sq = 0.f;
    for (int i = threadIdx.x; i < NEL; i += blockDim.x) {
        float v = xp[i];
        sum += v; sq += v * v;
    }
    sum = blockReduceSum(sum);
    sq  = blockReduceSum(sq);
    float mean = sum / (float)NEL;
    float var  = sq / (float)NEL - mean * mean;
    float inv  = rsqrtf(var + GN_EPS);

    for (int i = threadIdx.x; i < NEL; i += blockDim.x) {
        int ci = i / HW;
        int p  = i % HW;
        int c  = g * CPG + ci;
        float v = (xp[i] - mean) * inv * s[c] + bgn[c];
        out[((size_t)b * HW + p) * CCH + c] = v;
    }
}

// ---------------- LayerNorm ----------------
__global__ void layernorm_kernel(const float* __restrict__ x,
                                 const float* __restrict__ s,
                                 const float* __restrict__ b,
                                 float* __restrict__ out) {
    int row = blockIdx.x;
    const float* xr = x + (size_t)row * CCH;
    float sum = 0.f, sq = 0.f;
    for (int i = threadIdx.x; i < CCH; i += blockDim.x) {
        float v = xr[i];
        sum += v; sq += v * v;
    }
    sum = blockReduceSum(sum);
    sq  = blockReduceSum(sq);
    float mean = sum / (float)CCH;
    float var  = sq / (float)CCH - mean * mean;
    float inv  = rsqrtf(var + LN_EPS);
    float* o = out + (size_t)row * CCH;
    for (int i = threadIdx.x; i < CCH; i += blockDim.x)
        o[i] = (xr[i] - mean) * inv * s[i] + b[i];
}

// ---------------- tf32 helpers ----------------
__device__ __forceinline__ float f2tf32(float x) {
    uint32_t u;
    asm("cvt.rna.tf32.f32 %0, %1;" : "=r"(u) : "f"(x));
    return __uint_as_float(u);
}

__device__ __forceinline__ void mma4(float c[4], const float a[4], float b0, float b1) {
    asm volatile(
        "mma.sync.aligned.m16n8k8.row.col.f32.tf32.tf32.f32 "
        "{%0,%1,%2,%3}, {%4,%5,%6,%7}, {%8,%9}, {%0,%1,%2,%3};"
        : "+f"(c[0]), "+f"(c[1]), "+f"(c[2]), "+f"(c[3])
        : "r"(__float_as_uint(a[0])), "r"(__float_as_uint(a[1])),
          "r"(__float_as_uint(a[2])), "r"(__float_as_uint(a[3])),
          "r"(__float_as_uint(b0)), "r"(__float_as_uint(b1)));
}

// ---------------- tf32 tensor-core batched GEMM ----------------
// 128 x NT block tile, 8 warps (4x2), fragment-major smem.
// Requires: K % 16 == 0, lda % 4 == 0, ldb % 4 == 0, 16B-aligned A/B bases.
// TB=false: B(k,n)=Bm[k*ldb+n] (block n-range fully in bounds);
// TB=true:  B(k,n)=Bm[n*ldb+k].
template<bool TB, int NT>
__global__ __launch_bounds__(256)
void mma_gemm_kernel(const float* __restrict__ A, const float* __restrict__ Bm,
                     const float* __restrict__ bias, const float* __restrict__ res,
                     float* __restrict__ C,
                     int M, int N, int K, int lda, int ldb, int ldc,
                     long long sAo, long long sAi, long long sBo, long long sBi,
                     long long sCo, long long sCi, int inner, float alpha) {
    constexpr int NPW = NT / 32;
    constexpr int NJ  = NT / 16;
    constexpr int ASZ = 8 * 264;
    constexpr int BSZ = (NT / 16) * 264;
    constexpr int NB4 = (NT == 128) ? 2 : 1;

    int z  = blockIdx.z;
    int zo = z / inner, zi = z % inner;
    A  += (size_t)(zo * sAo + zi * sAi);
    Bm += (size_t)(zo * sBo + zi * sBi);
    long long coff = zo * sCo + zi * sCi;
    C += coff;
    if (res) res += coff;

    __shared__ float SA[2 * ASZ];
    __shared__ float SB[2 * BSZ];

    const int tid  = threadIdx.x;
    const int wid  = tid >> 5;
    const int lane = tid & 31;
    const int wr   = wid >> 1;
    const int wc   = wid & 1;
    const int gp   = lane >> 2;
    const int tg   = lane & 3;
    const int mBase = blockIdx.y * 128;
    const int nBase = blockIdx.x * NT;

    // ---- precompute A staging (loop-invariant) ----
    const float4* pA[2];
    int ofA[2];
#pragma unroll
    for (int u = 0; u < 2; u++) {
        int e = u * 256 + tid;
        int row = e >> 2, kq = e & 3;
        int gm = mBase + row;
        if (gm >= M) gm = 0;   // clamp: garbage lands in dead acc cells
        pA[u] = reinterpret_cast<const float4*>(A + (size_t)gm * lda) + kq;
        int sl = ((row >> 3) & 1) | ((kq & 1) << 1);
        ofA[u] = (row >> 4) * 264 + sl * 66 + (kq >> 1) * 33 + ((row & 7) << 2);
    }

    // ---- precompute B staging ----
    const float4* pB[NB4];
    int ofB[NB4];
#pragma unroll
    for (int u = 0; u < NB4; u++) {
        int e = u * 256 + tid;
        if (TB) {
            int n = e >> 2, kq = e & 3;
            int gn = nBase + n;
            if (gn >= N) gn = 0;
            pB[u] = reinterpret_cast<const float4*>(Bm + (size_t)gn * ldb) + kq;
            int sl = (((n >> 3) & 1) << 1) | (kq & 1);
            ofB[u] = (n >> 4) * 264 + sl * 66 + (kq >> 1) * 33 + ((n & 7) << 2);
        } else {
            int k, nq;
            if (NT == 128) { k = e >> 5; nq = e & 31; }
            else           { k = e >> 4; nq = e & 15; }
            pB[u] = reinterpret_cast<const float4*>(Bm + (size_t)k * ldb + nBase) + nq;
            int sl = (((nq >> 1) & 1) << 1) | ((k >> 2) & 1);
            ofB[u] = (nq >> 2) * 264 + sl * 66 + (k >> 3) * 33 + ((nq & 1) << 4) + (k & 3);
        }
    }
    // float4 step per 16-row k-tile:
    //   TB: 16 floats along contiguous k  -> 4 float4
    //   !TB: 16 rows of ldb floats        -> 4*ldb float4   (round-5 bug: was ldb)
    const long long stepB = TB ? 4LL : 4LL * (long long)ldb;

    float acc[2][NJ][4];
#pragma unroll
    for (int i = 0; i < 2; i++)
#pragma unroll
        for (int j = 0; j < NJ; j++)
#pragma unroll
            for (int q = 0; q < 4; q++) acc[i][j][q] = 0.f;

    float4 va[2], vb[NB4];

    auto loadTile = [&]() {
#pragma unroll
        for (int u = 0; u < 2; u++) { va[u] = *pA[u]; pA[u] += 4; }
#pragma unroll
        for (int u = 0; u < NB4; u++) { vb[u] = *pB[u]; pB[u] += stepB; }
    };
    auto storeTile = [&](int bf) {
        float* sa = SA + bf * ASZ;
        float* sb = SB + bf * BSZ;
#pragma unroll
        for (int u = 0; u < 2; u++) {
            sa[ofA[u] + 0] = f2tf32(va[u].x);
            sa[ofA[u] + 1] = f2tf32(va[u].y);
            sa[ofA[u] + 2] = f2tf32(va[u].z);
            sa[ofA[u] + 3] = f2tf32(va[u].w);
        }
#pragma unroll
        for (int u = 0; u < NB4; u++) {
            if (TB) {
                sb[ofB[u] + 0] = f2tf32(vb[u].x);
                sb[ofB[u] + 1] = f2tf32(vb[u].y);
                sb[ofB[u] + 2] = f2tf32(vb[u].z);
                sb[ofB[u] + 3] = f2tf32(vb[u].w);
            } else {
                sb[ofB[u] + 0]  = f2tf32(vb[u].x);
                sb[ofB[u] + 4]  = f2tf32(vb[u].y);
                sb[ofB[u] + 8]  = f2tf32(vb[u].z);
                sb[ofB[u] + 12] = f2tf32(vb[u].w);
            }
        }
    };

    loadTile();
    storeTile(0);
    __syncthreads();

    const int ktiles = K >> 4;
    const int aB = wr * 2 * 264 + lane;
    const int bB = wc * NPW * 264 + lane;

    for (int kt = 0; kt < ktiles; kt++) {
        const float* sa = SA + (kt & 1) * ASZ;
        const float* sb = SB + (kt & 1) * BSZ;
        bool more = (kt + 1 < ktiles);
        if (more) loadTile();

#pragma unroll
        for (int ks = 0; ks < 2; ks++) {
            float a0[4], a1[4];
#pragma unroll
            for (int s = 0; s < 4; s++) {
                a0[s] = sa[aB +       s * 66 + ks * 33];
                a1[s] = sa[aB + 264 + s * 66 + ks * 33];
            }
#pragma unroll
            for (int p = 0; p < NPW; p++) {
                float bb[4];
#pragma unroll
                for (int s = 0; s < 4; s++)
                    bb[s] = sb[bB + p * 264 + s * 66 + ks * 33];
                mma4(acc[0][2 * p    ], a0, bb[0], bb[1]);
                mma4(acc[1][2 * p    ], a1, bb[0], bb[1]);
                mma4(acc[0][2 * p + 1], a0, bb[2], bb[3]);
                mma4(acc[1][2 * p + 1], a1, bb[2], bb[3]);
            }
        }

        if (more) storeTile((kt + 1) & 1);
        __syncthreads();
    }

    // ---- epilogue ----
    const bool evenLdc = ((ldc & 1) == 0);
#pragma unroll
    for (int i = 0; i < 2; i++) {
#pragma unroll
        for (int j = 0; j < NJ; j++) {
            int r0 = mBase + wr * 32 + i * 16 + gp;
            int c0 = nBase + wc * (NT / 2) + j * 8 + tg * 2;
#pragma unroll
            for (int h = 0; h < 2; h++) {
                int row = r0 + h * 8;
                if (row >= M) continue;
                float v0 = acc[i][j][h * 2 + 0] * alpha;
                float v1 = acc[i][j][h * 2 + 1] * alpha;
                if (evenLdc && c0 + 1 < N) {
                    if (bias) { v0 += bias[c0]; v1 += bias[c0 + 1]; }
                    if (res) {
                        const float2 rr = *reinterpret_cast<const float2*>(&res[(size_t)row * ldc + c0]);
                        v0 += rr.x; v1 += rr.y;
                    }
                    float2 o; o.x = v0; o.y = v1;
                    *reinterpret_cast<float2*>(&C[(size_t)row * ldc + c0]) = o;
                } else {
                    if (c0 < N) {
                        if (bias) v0 += bias[c0];
                        if (res)  v0 += res[(size_t)row * ldc + c0];
                        C[(size_t)row * ldc + c0] = v0;
                    }
                    if (c0 + 1 < N) {
                        if (bias) v1 += bias[c0 + 1];
                        if (res)  v1 += res[(size_t)row * ldc + c0 + 1];
                        C[(size_t)row * ldc + c0 + 1] = v1;
                    }
                }
            }
        }
    }
}

// ---------------- softmax (row cached in smem, optional zero-pad) ----------
__global__ void softmax_kernel(float* __restrict__ sc, int len, int ld, int pad) {
    __shared__ float rowbuf[HW];
    float* p = sc + (size_t)blockIdx.x * ld;
    float mx = -INFINITY;
    for (int i = threadIdx.x; i < len; i += blockDim.x) {
        float v = p[i];
        rowbuf[i] = v;
        mx = fmaxf(mx, v);
    }
    mx = blockReduceMax(mx);
    float sum = 0.f;
    for (int i = threadIdx.x; i < len; i += blockDim.x) {
        float e = __expf(rowbuf[i] - mx);
        rowbuf[i] = e;
        sum += e;
    }
    sum = blockReduceSum(sum);
    float inv = 1.f / sum;
    for (int i = threadIdx.x; i < len; i += blockDim.x)
        p[i] = rowbuf[i] * inv;
    for (int i = len + threadIdx.x; i < pad; i += blockDim.x)
        p[i] = 0.f;
}

// ---------------- GEGLU ----------------
__global__ void geglu_kernel(const float* __restrict__ h, float* __restrict__ out) {
    size_t idx = (size_t)blockIdx.x * blockDim.x + threadIdx.x;
    size_t total = (size_t)MTOK * FFD;
    if (idx >= total) return;
    size_t row = idx / FFD;
    size_t col = idx % FFD;
    float a = h[row * (2 * FFD) + col];
    float g = h[row * (2 * FFD) + FFD + col];
    float gelu = 0.5f * g * (1.f + erff(g * 0.70710678118654752f));
    out[idx] = a * gelu;
}

// ---------------- final transpose + residual ----------------
__global__ void final_kernel(const float* __restrict__ proj,
                             const float* __restrict__ x,
                             float* __restrict__ out) {
    size_t idx = (size_t)blockIdx.x * blockDim.x + threadIdx.x;
    size_t total = (size_t)BATCH * CCH * HW;
    if (idx >= total) return;
    size_t p  = idx % HW;
    size_t bc = idx / HW;
    size_t c  = bc % CCH;
    size_t b  = bc / CCH;
    out[idx] = proj[((size_t)b * HW + p) * CCH + c] + x[idx];
}

// ---------------- host side ----------------
static void launch_gemm(bool tb, int nt, const float* A, const float* B,
                        const float* bias, const float* res, float* C,
                        int M, int N, int K, int lda, int ldb, int ldc,
                        int batches, int inner,
                        long long sAo, long long sAi, long long sBo, long long sBi,
                        long long sCo, long long sCi, float alpha) {
    dim3 grid((N + nt - 1) / nt, (M + 127) / 128, batches);
    dim3 block(256);
    if (tb) {
        if (nt == 128)
            mma_gemm_kernel<true, 128><<<grid, block>>>(A, B, bias, res, C, M, N, K, lda, ldb, ldc,
                                                        sAo, sAi, sBo, sBi, sCo, sCi, inner, alpha);
        else
            mma_gemm_kernel<true, 64><<<grid, block>>>(A, B, bias, res, C, M, N, K, lda, ldb, ldc,
                                                       sAo, sAi, sBo, sBi, sCo, sCi, inner, alpha);
    } else {
        if (nt == 128)
            mma_gemm_kernel<false, 128><<<grid, block>>>(A, B, bias, res, C, M, N, K, lda, ldb, ldc,
                                                         sAo, sAi, sBo, sBi, sCo, sCi, inner, alpha);
        else
            mma_gemm_kernel<false, 64><<<grid, block>>>(A, B, bias, res, C, M, N, K, lda, ldb, ldc,
                                                        sAo, sAi, sBo, sBi, sCo, sCi, inner, alpha);
    }
}

extern "C" void kernel_launch(void* const* d_in, const int* in_sizes, int n_in,
                              void* d_out, int out_size) {
    const float* x      = (const float*)d_in[0];
    const float* ctx    = (const float*)d_in[1];
    const float* gn_s   = (const float*)d_in[2];
    const float* gn_b   = (const float*)d_in[3];
    const float* pin_w  = (const float*)d_in[4];
    const float* pin_b  = (const float*)d_in[5];
    const float* ln1_s  = (const float*)d_in[6];
    const float* ln1_b  = (const float*)d_in[7];
    const float* wq1    = (const float*)d_in[8];
    const float* wk1    = (const float*)d_in[9];
    const float* wv1    = (const float*)d_in[10];
    const float* wo1    = (const float*)d_in[11];
    const float* bo1    = (const float*)d_in[12];
    const float* ln2_s  = (const float*)d_in[13];
    const float* ln2_b  = (const float*)d_in[14];
    const float* wq2    = (const float*)d_in[15];
    const float* wk2    = (const float*)d_in[16];
    const float* wv2    = (const float*)d_in[17];
    const float* wo2    = (const float*)d_in[18];
    const float* bo2    = (const float*)d_in[19];
    const float* ln3_s  = (const float*)d_in[20];
    const float* ln3_b  = (const float*)d_in[21];
    const float* ff_w1  = (const float*)d_in[22];
    const float* ff_b1  = (const float*)d_in[23];
    const float* ff_w2  = (const float*)d_in[24];
    const float* ff_b2  = (const float*)d_in[25];
    const float* pout_w = (const float*)d_in[26];
    const float* pout_b = (const float*)d_in[27];
    float* out = (float*)d_out;

    float *t, *tmp, *qkv, *ao, *scores, *ffh, *ffa, *w3, *w2c;
    cudaGetSymbolAddress((void**)&t,      g_t);
    cudaGetSymbolAddress((void**)&tmp,    g_tmp);
    cudaGetSymbolAddress((void**)&qkv,    g_qkv);
    cudaGetSymbolAddress((void**)&ao,     g_ao);
    cudaGetSymbolAddress((void**)&scores, g_scores);
    cudaGetSymbolAddress((void**)&ffh,    g_ffh);
    cudaGetSymbolAddress((void**)&ffa,    g_ffa);
    cudaGetSymbolAddress((void**)&w3,     g_w3);
    cudaGetSymbolAddress((void**)&w2c,    g_w2c);

    const float attn_scale = 0.125f;
    const int LD3 = 3 * CCH;
    const int LD2 = 2 * CCH;

    cudaMemcpy2DAsync(w3,         LD3 * 4, wq1, CCH * 4, CCH * 4, CCH, cudaMemcpyDeviceToDevice);
    cudaMemcpy2DAsync(w3 + CCH,   LD3 * 4, wk1, CCH * 4, CCH * 4, CCH, cudaMemcpyDeviceToDevice);
    cudaMemcpy2DAsync(w3 + 2*CCH, LD3 * 4, wv1, CCH * 4, CCH * 4, CCH, cudaMemcpyDeviceToDevice);
    cudaMemcpy2DAsync(w2c,        LD2 * 4, wk2, CCH * 4, CCH * 4, CCH, cudaMemcpyDeviceToDevice);
    cudaMemcpy2DAsync(w2c + CCH,  LD2 * 4, wv2, CCH * 4, CCH * 4, CCH, cudaMemcpyDeviceToDevice);

    groupnorm_kernel<<<BATCH * GN_GROUPS, 256>>>(x, gn_s, gn_b, tmp);

    launch_gemm(false, 128, tmp, pin_w, pin_b, nullptr, t, MTOK, CCH, CCH, CCH, CCH, CCH,
                1, 1, 0, 0, 0, 0, 0, 0, 1.f);

    // ---- self-attention ----
    layernorm_kernel<<<MTOK, 256>>>(t, ln1_s, ln1_b, tmp);
    launch_gemm(false, 128, tmp, w3, nullptr, nullptr, qkv, MTOK, 3 * CCH, CCH,
                CCH, LD3, LD3, 1, 1, 0, 0, 0, 0, 0, 0, 1.f);
    launch_gemm(true, 128, qkv, qkv + CCH, nullptr, nullptr, scores, HW, HW, DH,
                LD3, LD3, HW, BATCH * HEADS, HEADS,
                (long long)HW * LD3, DH, (long long)HW * LD3, DH,
                (long long)HEADS * HW * HW, (long long)HW * HW, attn_scale);
    softmax_kernel<<<BATCH * HEADS * HW, 256>>>(scores, HW, HW, HW);
    launch_gemm(false, 64, scores, qkv + 2 * CCH, nullptr, nullptr, ao, HW, DH, HW,
                HW, LD3, CCH, BATCH * HEADS, HEADS,
                (long long)HEADS * HW * HW, (long long)HW * HW,
                (long long)HW * LD3, DH,
                (long long)HW * CCH, DH, 1.f);
    launch_gemm(false, 128, ao, wo1, bo1, t, t, MTOK, CCH, CCH, CCH, CCH, CCH,
                1, 1, 0, 0, 0, 0, 0, 0, 1.f);

    // ---- cross-attention (scores padded to ld=CTXP) ----
    layernorm_kernel<<<MTOK, 256>>>(t, ln2_s, ln2_b, tmp);
    launch_gemm(false, 128, tmp, wq2, nullptr, nullptr, qkv, MTOK, CCH, CCH,
                CCH, CCH, LD3, 1, 1, 0, 0, 0, 0, 0, 0, 1.f);
    launch_gemm(false, 128, ctx, w2c, nullptr, nullptr, qkv + CCH, BATCH * CTXL, 2 * CCH, CCH,
                CCH, LD2, LD3, 1, 1, 0, 0, 0, 0, 0, 0, 1.f);
    launch_gemm(true, 64, qkv, qkv + CCH, nullptr, nullptr, scores, HW, CTXL, DH,
                LD3, LD3, CTXP, BATCH * HEADS, HEADS,
                (long long)HW * LD3, DH, (long long)CTXL * LD3, DH,
                (long long)HEADS * HW * CTXP, (long long)HW * CTXP, attn_scale);
    softmax_kernel<<<BATCH * HEADS * HW, 256>>>(scores, CTXL, CTXP, CTXP);
    // K padded to CTXP=80 — pad score cols are zero, so extra V rows are inert
    launch_gemm(false, 64, scores, qkv + 2 * CCH, nullptr, nullptr, ao, HW, DH, CTXP,
                CTXP, LD3, CCH, BATCH * HEADS, HEADS,
                (long long)HEADS * HW * CTXP, (long long)HW * CTXP,
                (long long)CTXL * LD3, DH,
                (long long)HW * CCH, DH, 1.f);
    launch_gemm(false, 128, ao, wo2, bo2, t, t, MTOK, CCH, CCH, CCH, CCH, CCH,
                1, 1, 0, 0, 0, 0, 0, 0, 1.f);

    // ---- GEGLU FF ----
    layernorm_kernel<<<MTOK, 256>>>(t, ln3_s, ln3_b, tmp);
    launch_gemm(false, 128, tmp, ff_w1, ff_b1, nullptr, ffh, MTOK, 2 * FFD, CCH,
                CCH, 2 * FFD, 2 * FFD, 1, 1, 0, 0, 0, 0, 0, 0, 1.f);
    {
        size_t total = (size_t)MTOK * FFD;
        geglu_kernel<<<(int)((total + 255) / 256), 256>>>(ffh, ffa);
    }
    launch_gemm(false, 128, ffa, ff_w2, ff_b2, t, t, MTOK, CCH, FFD, FFD, CCH, CCH,
                1, 1, 0, 0, 0, 0, 0, 0, 1.f);

    // ---- proj_out + residual ----
    launch_gemm(false, 128, t, pout_w, pout_b, nullptr, tmp, MTOK, CCH, CCH, CCH, CCH, CCH,
                1, 1, 0, 0, 0, 0, 0, 0, 1.f);
    {
        size_t total = (size_t)BATCH * CCH * HW;
        final_kernel<<<(int)((total + 255) / 256), 256>>>(tmp, x, out);
    }
}